// round 2
// baseline (speedup 1.0000x reference)
#include <cuda_runtime.h>
#include <cuda_bf16.h>
#include <cstdint>

// ---------------------------------------------------------------------------
// KTBCrossAttention restructured:
//   G_mb   = X_mbᵀ X_mb                  (768x768, K=4096, symmetric)  [3xTF32 mma]
//   U_mb   = W_k,mᵀ G_mb                 (768x768, K=768)              [3xTF32 mma]
//   L_mbh  = s * U_mb[h*64:,:] @ Wv_h    (64x64, K=768) -> softmax over d -> ctx
//   out_m' = X_m' @ blockdiag(ctx_{1-m'})                              [tf32 mma]
// ---------------------------------------------------------------------------

#define DIMC 768
#define NTOK 4096
#define BATCH 16
#define NHEADS 12
#define HD 64

__device__ float g_G[2][BATCH][DIMC * DIMC];            // 75.5 MB
__device__ float g_U[2][BATCH][DIMC * DIMC];            // 75.5 MB
__device__ float g_ctx[2][BATCH][NHEADS][HD * HD];      // 6.3 MB

__device__ __forceinline__ void mma_tf32(float* d, const uint32_t* a, const uint32_t* b) {
    asm volatile(
        "mma.sync.aligned.m16n8k8.row.col.f32.tf32.tf32.f32 "
        "{%0,%1,%2,%3}, {%4,%5,%6,%7}, {%8,%9}, {%0,%1,%2,%3};"
        : "+f"(d[0]), "+f"(d[1]), "+f"(d[2]), "+f"(d[3])
        : "r"(a[0]), "r"(a[1]), "r"(a[2]), "r"(a[3]), "r"(b[0]), "r"(b[1]));
}

__device__ __forceinline__ void split_tf32(float v, uint32_t& hi, uint32_t& lo) {
    asm("cvt.rna.tf32.f32 %0, %1;" : "=r"(hi) : "f"(v));
    float r = v - __uint_as_float(hi);
    asm("cvt.rna.tf32.f32 %0, %1;" : "=r"(lo) : "f"(r));
}

__device__ __forceinline__ uint32_t to_tf32(float v) {
    uint32_t t;
    asm("cvt.rna.tf32.f32 %0, %1;" : "=r"(t) : "f"(v));
    return t;
}

// ---------------------------------------------------------------------------
// Generic C = Aᵀ B, M=N=768, 128x128 CTA tile, KB=16, 3xTF32 split precision.
// A is stored [K, M] with row stride lda (so A-frag element A[i,k] = A[k*lda+i]).
// B is stored [K, N] with row stride ldb.
// sym=1: only upper-triangular tiles launched; mirror tile written transposed.
// ---------------------------------------------------------------------------
__global__ __launch_bounds__(256) void gemm_tt_kernel(
    const float* __restrict__ A, long long aStr,
    const float* __restrict__ B, long long bStr,
    float* __restrict__ C, long long cStr,
    int K, int lda, int ldb, int sym)
{
    __shared__ uint32_t Ash[128][20], Alo[128][20], Bsh[128][20], Blo[128][20];

    const int z = blockIdx.y;
    const float* Ab = A + (long long)z * aStr;
    const float* Bb = B + (long long)z * bStr;
    float* Cb = C + (long long)z * cStr;

    int ti, tj;
    if (sym) {
        int rem = blockIdx.x;
        ti = 0;
        while (rem >= 6 - ti) { rem -= (6 - ti); ti++; }
        tj = ti + rem;
    } else {
        ti = blockIdx.x / 6;
        tj = blockIdx.x % 6;
    }
    const int ci0 = ti * 128, cj0 = tj * 128;

    const int tid = threadIdx.x;
    const int wid = tid >> 5, lane = tid & 31;
    const int wm = wid >> 2, wn = wid & 3;
    const int grp = lane >> 2, qid = lane & 3;

    float acc[4][4][4];
#pragma unroll
    for (int a = 0; a < 4; a++)
#pragma unroll
        for (int b = 0; b < 4; b++)
#pragma unroll
            for (int c = 0; c < 4; c++) acc[a][b][c] = 0.f;

    // loader indices: 512 float4 per matrix tile (16 rows x 128 cols), 2 per thread
    const int f40 = tid, f41 = tid + 256;
    const int kk0 = f40 >> 5, cc0 = (f40 & 31) << 2;
    const int kk1 = f41 >> 5, cc1 = (f41 & 31) << 2;

    const float* a0p = Ab + (long long)kk0 * lda + ci0 + cc0;
    const float* a1p = Ab + (long long)kk1 * lda + ci0 + cc1;
    const float* b0p = Bb + (long long)kk0 * ldb + cj0 + cc0;
    const float* b1p = Bb + (long long)kk1 * ldb + cj0 + cc1;

    float4 ra0 = *(const float4*)a0p;
    float4 ra1 = *(const float4*)a1p;
    float4 rb0 = *(const float4*)b0p;
    float4 rb1 = *(const float4*)b1p;

    for (int k0 = 0; k0 < K; k0 += 16) {
        // split + store staged regs to smem
        {
            uint32_t h, l;
            split_tf32(ra0.x, h, l); Ash[cc0 + 0][kk0] = h; Alo[cc0 + 0][kk0] = l;
            split_tf32(ra0.y, h, l); Ash[cc0 + 1][kk0] = h; Alo[cc0 + 1][kk0] = l;
            split_tf32(ra0.z, h, l); Ash[cc0 + 2][kk0] = h; Alo[cc0 + 2][kk0] = l;
            split_tf32(ra0.w, h, l); Ash[cc0 + 3][kk0] = h; Alo[cc0 + 3][kk0] = l;
            split_tf32(ra1.x, h, l); Ash[cc1 + 0][kk1] = h; Alo[cc1 + 0][kk1] = l;
            split_tf32(ra1.y, h, l); Ash[cc1 + 1][kk1] = h; Alo[cc1 + 1][kk1] = l;
            split_tf32(ra1.z, h, l); Ash[cc1 + 2][kk1] = h; Alo[cc1 + 2][kk1] = l;
            split_tf32(ra1.w, h, l); Ash[cc1 + 3][kk1] = h; Alo[cc1 + 3][kk1] = l;
            split_tf32(rb0.x, h, l); Bsh[cc0 + 0][kk0] = h; Blo[cc0 + 0][kk0] = l;
            split_tf32(rb0.y, h, l); Bsh[cc0 + 1][kk0] = h; Blo[cc0 + 1][kk0] = l;
            split_tf32(rb0.z, h, l); Bsh[cc0 + 2][kk0] = h; Blo[cc0 + 2][kk0] = l;
            split_tf32(rb0.w, h, l); Bsh[cc0 + 3][kk0] = h; Blo[cc0 + 3][kk0] = l;
            split_tf32(rb1.x, h, l); Bsh[cc1 + 0][kk1] = h; Blo[cc1 + 0][kk1] = l;
            split_tf32(rb1.y, h, l); Bsh[cc1 + 1][kk1] = h; Blo[cc1 + 1][kk1] = l;
            split_tf32(rb1.z, h, l); Bsh[cc1 + 2][kk1] = h; Blo[cc1 + 2][kk1] = l;
            split_tf32(rb1.w, h, l); Bsh[cc1 + 3][kk1] = h; Blo[cc1 + 3][kk1] = l;
        }
        __syncthreads();

        if (k0 + 16 < K) {  // prefetch next K-slab while computing
            a0p += (long long)16 * lda; a1p += (long long)16 * lda;
            b0p += (long long)16 * ldb; b1p += (long long)16 * ldb;
            ra0 = *(const float4*)a0p; ra1 = *(const float4*)a1p;
            rb0 = *(const float4*)b0p; rb1 = *(const float4*)b1p;
        }

#pragma unroll
        for (int ks = 0; ks < 2; ks++) {
            const int kq = (ks << 3) + qid;
            uint32_t ah[4][4], al[4][4], bhf[4][2], blf[4][2];
#pragma unroll
            for (int mi = 0; mi < 4; mi++) {
                const int i = wm * 64 + mi * 16 + grp;
                ah[mi][0] = Ash[i][kq];     ah[mi][1] = Ash[i + 8][kq];
                ah[mi][2] = Ash[i][kq + 4]; ah[mi][3] = Ash[i + 8][kq + 4];
                al[mi][0] = Alo[i][kq];     al[mi][1] = Alo[i + 8][kq];
                al[mi][2] = Alo[i][kq + 4]; al[mi][3] = Alo[i + 8][kq + 4];
            }
#pragma unroll
            for (int nj = 0; nj < 4; nj++) {
                const int n = wn * 32 + nj * 8 + grp;
                bhf[nj][0] = Bsh[n][kq]; bhf[nj][1] = Bsh[n][kq + 4];
                blf[nj][0] = Blo[n][kq]; blf[nj][1] = Blo[n][kq + 4];
            }
#pragma unroll
            for (int mi = 0; mi < 4; mi++)
#pragma unroll
                for (int nj = 0; nj < 4; nj++) {
                    mma_tf32(acc[mi][nj], ah[mi], bhf[nj]);   // hi*hi
                    mma_tf32(acc[mi][nj], al[mi], bhf[nj]);   // lo*hi
                    mma_tf32(acc[mi][nj], ah[mi], blf[nj]);   // hi*lo
                }
        }
        __syncthreads();
    }

    // epilogue
#pragma unroll
    for (int mi = 0; mi < 4; mi++) {
        const int r0 = ci0 + wm * 64 + mi * 16 + grp;
#pragma unroll
        for (int nj = 0; nj < 4; nj++) {
            const int c0c = cj0 + wn * 32 + nj * 8 + 2 * qid;
            float2 v01 = make_float2(acc[mi][nj][0], acc[mi][nj][1]);
            float2 v23 = make_float2(acc[mi][nj][2], acc[mi][nj][3]);
            *(float2*)(Cb + (long long)r0 * DIMC + c0c) = v01;
            *(float2*)(Cb + (long long)(r0 + 8) * DIMC + c0c) = v23;
            if (sym && ti != tj) {
                Cb[(long long)(c0c) * DIMC + r0]         = acc[mi][nj][0];
                Cb[(long long)(c0c + 1) * DIMC + r0]     = acc[mi][nj][1];
                Cb[(long long)(c0c) * DIMC + r0 + 8]     = acc[mi][nj][2];
                Cb[(long long)(c0c + 1) * DIMC + r0 + 8] = acc[mi][nj][3];
            }
        }
    }
}

// ---------------------------------------------------------------------------
// Per (m,b,h): L[d][e] = SCALE * sum_c U[h*64+d][c] * W[c][768+h*64+e]
// then column-wise (over d) softmax -> g_ctx[m][b][h]
// ---------------------------------------------------------------------------
__global__ __launch_bounds__(256) void ctx_kernel(
    const float* __restrict__ Wrgb, const float* __restrict__ Wdepth)
{
    __shared__ float Us[64][68];
    __shared__ float Ws[64][68];

    const int z = blockIdx.y;
    const int m = z >> 4, b = z & 15;
    const int h = blockIdx.x;
    const float* U = &g_U[m][b][0] + (long long)(h * 64) * DIMC;
    const float* W = (m == 0 ? Wrgb : Wdepth) + DIMC + h * 64;  // V columns of head h

    const int tid = threadIdx.x;
    const int ty = tid >> 4, tx = tid & 15;

    float acc[4][4];
#pragma unroll
    for (int i = 0; i < 4; i++)
#pragma unroll
        for (int j = 0; j < 4; j++) acc[i][j] = 0.f;

    for (int c0 = 0; c0 < DIMC; c0 += 64) {
#pragma unroll
        for (int t = 0; t < 4; t++) {
            const int f4 = tid + t * 256;          // 1024 float4 per tile
            const int r = f4 >> 4;
            const int cg = (f4 & 15) << 2;
            float4 u = *(const float4*)(U + (long long)r * DIMC + c0 + cg);
            Us[r][cg + 0] = u.x; Us[r][cg + 1] = u.y; Us[r][cg + 2] = u.z; Us[r][cg + 3] = u.w;
            float4 w = *(const float4*)(W + (long long)(c0 + r) * (2 * DIMC) + cg);
            Ws[r][cg + 0] = w.x; Ws[r][cg + 1] = w.y; Ws[r][cg + 2] = w.z; Ws[r][cg + 3] = w.w;
        }
        __syncthreads();
#pragma unroll 8
        for (int c = 0; c < 64; c++) {
            float u0 = Us[ty * 4 + 0][c], u1 = Us[ty * 4 + 1][c];
            float u2 = Us[ty * 4 + 2][c], u3 = Us[ty * 4 + 3][c];
            float w0 = Ws[c][tx * 4 + 0], w1 = Ws[c][tx * 4 + 1];
            float w2 = Ws[c][tx * 4 + 2], w3 = Ws[c][tx * 4 + 3];
            acc[0][0] += u0 * w0; acc[0][1] += u0 * w1; acc[0][2] += u0 * w2; acc[0][3] += u0 * w3;
            acc[1][0] += u1 * w0; acc[1][1] += u1 * w1; acc[1][2] += u1 * w2; acc[1][3] += u1 * w3;
            acc[2][0] += u2 * w0; acc[2][1] += u2 * w1; acc[2][2] += u2 * w2; acc[2][3] += u2 * w3;
            acc[3][0] += u3 * w0; acc[3][1] += u3 * w1; acc[3][2] += u3 * w2; acc[3][3] += u3 * w3;
        }
        __syncthreads();
    }

    // write L (scaled) into Us, then softmax over d per column e
    const float SCALE = 0.125f;  // 64^-0.5
#pragma unroll
    for (int i = 0; i < 4; i++)
#pragma unroll
        for (int j = 0; j < 4; j++)
            Us[ty * 4 + i][tx * 4 + j] = acc[i][j] * SCALE;
    __syncthreads();

    if (tid < 64) {
        const int e = tid;
        float mx = -1e30f;
#pragma unroll 8
        for (int d = 0; d < 64; d++) mx = fmaxf(mx, Us[d][e]);
        float s = 0.f;
#pragma unroll 8
        for (int d = 0; d < 64; d++) {
            float v = expf(Us[d][e] - mx);
            Us[d][e] = v;
            s += v;
        }
        const float inv = 1.f / s;
        float* cx = &g_ctx[m][b][h][0];
#pragma unroll 8
        for (int d = 0; d < 64; d++) cx[d * 64 + e] = Us[d][e] * inv;
    }
}

// ---------------------------------------------------------------------------
// out_m[b, n, h*64+e] = sum_d X_m[b, n, h*64+d] * ctx_{1-m}[b][h][d][e]
// 64-row tiles, tf32 mma, K=64.
// ---------------------------------------------------------------------------
__global__ __launch_bounds__(256) void out_kernel(
    const float* __restrict__ rgb, const float* __restrict__ depth,
    float* __restrict__ out)
{
    __shared__ uint32_t As[64][68];
    __shared__ uint32_t Bs[64][68];

    const int z = blockIdx.z;
    const int m = z >> 4, b = z & 15;
    const int h = blockIdx.y;
    const int n0 = blockIdx.x * 64;

    const float* X = (m == 0 ? rgb : depth) + ((long long)b * NTOK + n0) * DIMC + h * HD;
    const float* cx = &g_ctx[1 - m][b][h][0];
    float* O = out + (long long)m * BATCH * NTOK * DIMC + ((long long)b * NTOK + n0) * DIMC + h * HD;

    const int tid = threadIdx.x;
    const int wid = tid >> 5, lane = tid & 31;
    const int wm = wid >> 2, wn = wid & 3;
    const int grp = lane >> 2, qid = lane & 3;

    // load X tile [64 rows][64 cols], row-major, cvt tf32
#pragma unroll
    for (int t = 0; t < 4; t++) {
        const int f4 = tid + t * 256;
        const int r = f4 >> 4;
        const int cg = (f4 & 15) << 2;
        float4 v = *(const float4*)(X + (long long)r * DIMC + cg);
        As[r][cg + 0] = to_tf32(v.x); As[r][cg + 1] = to_tf32(v.y);
        As[r][cg + 2] = to_tf32(v.z); As[r][cg + 3] = to_tf32(v.w);
    }
    // load ctx [d][e] transposed -> Bs[e][d]
#pragma unroll
    for (int t = 0; t < 4; t++) {
        const int f4 = tid + t * 256;
        const int d = f4 >> 4;
        const int eg = (f4 & 15) << 2;
        float4 v = *(const float4*)(cx + d * 64 + eg);
        Bs[eg + 0][d] = to_tf32(v.x); Bs[eg + 1][d] = to_tf32(v.y);
        Bs[eg + 2][d] = to_tf32(v.z); Bs[eg + 3][d] = to_tf32(v.w);
    }
    __syncthreads();

    float acc[2][2][4];
#pragma unroll
    for (int a = 0; a < 2; a++)
#pragma unroll
        for (int c = 0; c < 2; c++)
#pragma unroll
            for (int r = 0; r < 4; r++) acc[a][c][r] = 0.f;

#pragma unroll
    for (int ks = 0; ks < 8; ks++) {
        const int kq = (ks << 3) + qid;
        uint32_t ah[2][4], bh[2][2];
#pragma unroll
        for (int mi = 0; mi < 2; mi++) {
            const int i = wm * 32 + mi * 16 + grp;
            ah[mi][0] = As[i][kq];     ah[mi][1] = As[i + 8][kq];
            ah[mi][2] = As[i][kq + 4]; ah[mi][3] = As[i + 8][kq + 4];
        }
#pragma unroll
        for (int nj = 0; nj < 2; nj++) {
            const int n = wn * 16 + nj * 8 + grp;
            bh[nj][0] = Bs[n][kq]; bh[nj][1] = Bs[n][kq + 4];
        }
#pragma unroll
        for (int mi = 0; mi < 2; mi++)
#pragma unroll
            for (int nj = 0; nj < 2; nj++)
                mma_tf32(acc[mi][nj], ah[mi], bh[nj]);
    }

#pragma unroll
    for (int mi = 0; mi < 2; mi++) {
        const int r0 = wm * 32 + mi * 16 + grp;
#pragma unroll
        for (int nj = 0; nj < 2; nj++) {
            const int c0c = wn * 16 + nj * 8 + 2 * qid;
            *(float2*)(O + (long long)r0 * DIMC + c0c) =
                make_float2(acc[mi][nj][0], acc[mi][nj][1]);
            *(float2*)(O + (long long)(r0 + 8) * DIMC + c0c) =
                make_float2(acc[mi][nj][2], acc[mi][nj][3]);
        }
    }
}

// ---------------------------------------------------------------------------
extern "C" void kernel_launch(void* const* d_in, const int* in_sizes, int n_in,
                              void* d_out, int out_size)
{
    const float* rgb = (const float*)d_in[0];
    const float* dep = (const float*)d_in[1];
    const float* Wr  = (const float*)d_in[2];
    const float* Wd  = (const float*)d_in[3];
    float* out = (float*)d_out;

    float* pG = nullptr;
    float* pU = nullptr;
    cudaGetSymbolAddress((void**)&pG, g_G);
    cudaGetSymbolAddress((void**)&pU, g_U);

    const long long SB = (long long)DIMC * DIMC;       // 589824
    const long long SX = (long long)NTOK * DIMC;

    // G = XᵀX (symmetric: 21 tiles)
    gemm_tt_kernel<<<dim3(21, 16), 256>>>(rgb, SX, rgb, SX, pG, SB, NTOK, DIMC, DIMC, 1);
    gemm_tt_kernel<<<dim3(21, 16), 256>>>(dep, SX, dep, SX, pG + 16 * SB, SB, NTOK, DIMC, DIMC, 1);

    // U = Wkᵀ G  (Wk = first 768 columns of W, lda = 1536)
    gemm_tt_kernel<<<dim3(36, 16), 256>>>(Wr, 0LL, pG, SB, pU, SB, DIMC, 2 * DIMC, DIMC, 0);
    gemm_tt_kernel<<<dim3(36, 16), 256>>>(Wd, 0LL, pG + 16 * SB, SB, pU + 16 * SB, SB, DIMC, 2 * DIMC, DIMC, 0);

    // per-head 64x64 logits + softmax -> ctx
    ctx_kernel<<<dim3(NHEADS, 32), 256>>>(Wr, Wd);

    // out = X @ blockdiag(ctx_other)
    out_kernel<<<dim3(NTOK / 64, NHEADS, 32), 256>>>(rgb, dep, out);
}

// round 4
// speedup vs baseline: 1.4227x; 1.4227x over previous
#include <cuda_runtime.h>
#include <cuda_bf16.h>
#include <cstdint>

// ---------------------------------------------------------------------------
// KTBCrossAttention restructured (mma.sync + fragment-packed operands):
//   Xp_hi/lo = pack(split(Xᵀ))   fragment-ordered global arrays (pre-pass)
//   G_mb     = XᵀX   (768x768, K=4096, sym)  [3xTF32 mma.sync, cp.async pipe]
//   U_mb     = WkᵀG  (768x768, K=768)        [3xTF32 mma.sync]
//   ctx      = softmax_d( s * U[h] @ Wv_h )
//   out_m'   = X_m' @ blockdiag(ctx_{1-m'})  [SIMT tf32 mma]
//
// Pack layout for matrix M[R][K] (K-major logical):
//   block = (r>>4)*(K>>3) + (k>>3)          (16r x 8k tf32 block, 128 elems)
//   within: lane = (r&7)*4 + (k&3), reg = ((r>>3)&1) + 2*((k>>2)&1)
//   elem offset = block*128 + lane*4 + reg
// A-frag(16x8) = one LDS.128 per lane. B-frags of both 8-col halves of a
// 16-row block come from the same LDS.128: regs {x,z} and {y,w}.
// ---------------------------------------------------------------------------

#define DIMC 768
#define NTOK 4096
#define BATCH 16
#define NHEADS 12
#define HD 64

#define KB 16
#define STAGES 4
#define STAGE_BYTES 32768
#define GEMM_SMEM (STAGES * STAGE_BYTES)   // 128 KB

// scratch (device globals; allocation-free contract)
__device__ uint32_t g_Xphi[2][BATCH][DIMC * NTOK];     // 402.6 MB
__device__ uint32_t g_Xplo[2][BATCH][DIMC * NTOK];     // 402.6 MB
__device__ uint32_t g_Wphi[2][DIMC * DIMC];            // 2.4 MB
__device__ uint32_t g_Wplo[2][DIMC * DIMC];
__device__ uint32_t g_Gphi[2][BATCH][DIMC * DIMC];     // 75.5 MB
__device__ uint32_t g_Gplo[2][BATCH][DIMC * DIMC];     // 75.5 MB
__device__ float    g_U[2][BATCH][DIMC * DIMC];        // 75.5 MB
__device__ float    g_ctx[2][BATCH][NHEADS][HD * HD];  // 6.3 MB

// ---------------------------------------------------------------------------
__device__ __forceinline__ uint32_t smem_to_u32(const void* p) {
    uint32_t a;
    asm("{ .reg .u64 tmp; cvta.to.shared.u64 tmp, %1; cvt.u32.u64 %0, tmp; }"
        : "=r"(a) : "l"(p));
    return a;
}

__device__ __forceinline__ void cp16(uint32_t saddr, const void* g) {
    asm volatile("cp.async.cg.shared.global [%0], [%1], 16;" :: "r"(saddr), "l"(g));
}
#define CP_COMMIT() asm volatile("cp.async.commit_group;" ::: "memory")
#define CP_WAIT(n)  asm volatile("cp.async.wait_group %0;" :: "n"(n) : "memory")

__device__ __forceinline__ uint4 lds128(uint32_t a) {
    uint4 v;
    asm volatile("ld.shared.v4.b32 {%0,%1,%2,%3}, [%4];"
                 : "=r"(v.x), "=r"(v.y), "=r"(v.z), "=r"(v.w) : "r"(a));
    return v;
}

__device__ __forceinline__ void mma_tf32(float* d, const uint32_t* a, const uint32_t* b) {
    asm volatile(
        "mma.sync.aligned.m16n8k8.row.col.f32.tf32.tf32.f32 "
        "{%0,%1,%2,%3}, {%4,%5,%6,%7}, {%8,%9}, {%0,%1,%2,%3};"
        : "+f"(d[0]), "+f"(d[1]), "+f"(d[2]), "+f"(d[3])
        : "r"(a[0]), "r"(a[1]), "r"(a[2]), "r"(a[3]), "r"(b[0]), "r"(b[1]));
}

__device__ __forceinline__ void split_tf32(float v, uint32_t& hi, uint32_t& lo) {
    asm("cvt.rna.tf32.f32 %0, %1;" : "=r"(hi) : "f"(v));
    float r = v - __uint_as_float(hi);
    asm("cvt.rna.tf32.f32 %0, %1;" : "=r"(lo) : "f"(r));
}

__device__ __forceinline__ uint32_t to_tf32(float v) {
    uint32_t t;
    asm("cvt.rna.tf32.f32 %0, %1;" : "=r"(t) : "f"(v));
    return t;
}

__device__ __forceinline__ void pack_store(uint32_t* __restrict__ hi,
                                           uint32_t* __restrict__ lo,
                                           int r_, int k_, int Kb,
                                           uint32_t h, uint32_t l) {
    long long off = (long long)((r_ >> 4) * Kb + (k_ >> 3)) * 128
                  + ((r_ & 7) * 4 + (k_ & 3)) * 4
                  + ((r_ >> 3) & 1) + 2 * ((k_ >> 2) & 1);
    hi[off] = h;
    lo[off] = l;
}

// ---------------------------------------------------------------------------
// Pre-pass: read src[k][r] (row stride srcLd), transpose via smem, split to
// tf32 hi/lo, write fragment-packed arrays (coalesced). Tile = 64r x 64k.
// ---------------------------------------------------------------------------
__global__ __launch_bounds__(256) void pack_split_kernel(
    const float* __restrict__ src, long long srcBStr, int srcLd, int K,
    uint32_t* __restrict__ oHi, uint32_t* __restrict__ oLo, long long dstBStr)
{
    __shared__ float t[64][65];
    const int b = blockIdx.z;
    src += (long long)b * srcBStr;
    oHi += (long long)b * dstBStr;
    oLo += (long long)b * dstBStr;

    const int r0 = blockIdx.x * 64, k0 = blockIdx.y * 64;
    const int tid = threadIdx.x;
    const int Kb = K >> 3;

#pragma unroll
    for (int it = 0; it < 16; it++) {
        const int row = it * 4 + (tid >> 6);   // k-local
        const int col = tid & 63;              // r-local
        t[row][col] = src[(long long)(k0 + row) * srcLd + r0 + col];
    }
    __syncthreads();

#pragma unroll
    for (int it = 0; it < 16; it++) {
        const int e = it * 256 + tid;     // 4096 elems per tile
        const int w = e & 127;
        const int blk = e >> 7;
        const int mb = blk >> 3, kb = blk & 7;
        const int lane = w >> 2, reg = w & 3;
        const int rr = mb * 16 + (lane >> 2) + 8 * (reg & 1);
        const int kk = kb * 8 + (lane & 3) + 4 * ((reg >> 1) & 1);
        uint32_t h, l;
        split_tf32(t[kk][rr], h, l);
        const long long gidx =
            (long long)(((r0 >> 4) + mb) * Kb + (k0 >> 3) + kb) * 128 + w;
        oHi[gidx] = h;
        oLo[gidx] = l;
    }
}

// ---------------------------------------------------------------------------
// GEMM C = AᵀB (both operands fragment-packed hi/lo), 128x128 CTA tile,
// KB=16 slab, 4-stage cp.async pipeline, 3xTF32 mma.sync.
// sym=1: triangular tiles of G; epilogue splits C into G-pack (both mirrors).
// sym=0: full 6x6 tiles; epilogue writes row-major f32 (U).
// ---------------------------------------------------------------------------
__global__ __launch_bounds__(256) void gemm_tc_kernel(
    const uint32_t* __restrict__ Ahi, const uint32_t* __restrict__ Alo,
    long long aBStr,
    const uint32_t* __restrict__ Bhi, const uint32_t* __restrict__ Blo,
    long long bBStr,
    int K, int sym,
    uint32_t* __restrict__ oHi, uint32_t* __restrict__ oLo,
    float* __restrict__ oF, long long oBStr)
{
    extern __shared__ char smem[];
    const uint32_t smem_base = smem_to_u32(smem);
    const int tid = threadIdx.x;
    const int wid = tid >> 5, lane = tid & 31;
    const int wm = wid >> 2, wn = wid & 3;
    const int grp = lane >> 2, qid = lane & 3;
    const int z = blockIdx.y;

    Ahi += z * aBStr; Alo += z * aBStr;
    Bhi += z * bBStr; Blo += z * bBStr;
    if (oHi) { oHi += z * oBStr; oLo += z * oBStr; }
    if (oF)  { oF  += z * oBStr; }

    int ti, tj;
    if (sym) {
        int rem = blockIdx.x;
        ti = 0;
        while (rem >= 6 - ti) { rem -= (6 - ti); ti++; }
        tj = ti + rem;
    } else {
        ti = blockIdx.x / 6;
        tj = blockIdx.x % 6;
    }
    const int ci0 = ti * 128, cj0 = tj * 128;
    const int Kb = K >> 3;
    const int NS = K / KB;

    // per-thread copy role: quarter q (Ahi/Alo/Bhi/Blo), 64 threads each
    const int q = tid >> 6, t6 = tid & 63, mb = t6 >> 3, seg = t6 & 7;
    const uint32_t* gq = (q == 0) ? Ahi : (q == 1) ? Alo : (q == 2) ? Bhi : Blo;
    const int rowblk0 = ((q < 2) ? ci0 : cj0) >> 4;
    const uint32_t* gsrc = gq + (long long)(rowblk0 + mb) * Kb * 128 + seg * 32;
    const uint32_t sdst0 = smem_base + q * 8192 + t6 * 128;

    float acc[4][4][4];
#pragma unroll
    for (int a = 0; a < 4; a++)
#pragma unroll
        for (int b = 0; b < 4; b++)
#pragma unroll
            for (int c = 0; c < 4; c++) acc[a][b][c] = 0.f;

    // prologue: stages 0..2
#pragma unroll
    for (int s = 0; s < STAGES - 1; s++) {
        const uint32_t* g = gsrc + (long long)(s * 2) * 128;
        const uint32_t d = sdst0 + s * STAGE_BYTES;
#pragma unroll
        for (int i = 0; i < 8; i++) cp16(d + i * 16, g + i * 4);
        CP_COMMIT();
    }

    for (int s = 0; s < NS; s++) {
        if (s + STAGES - 1 < NS) {
            const int sp = s + STAGES - 1;
            const uint32_t* g = gsrc + (long long)(sp * 2) * 128;
            const uint32_t d = sdst0 + (sp & (STAGES - 1)) * STAGE_BYTES;
#pragma unroll
            for (int i = 0; i < 8; i++) cp16(d + i * 16, g + i * 4);
        }
        CP_COMMIT();
        CP_WAIT(STAGES - 1);
        __syncthreads();

        const uint32_t st = smem_base + (s & (STAGES - 1)) * STAGE_BYTES;
#pragma unroll
        for (int kk = 0; kk < 2; kk++) {
            uint4 ah[4], al[4], bh[2], bl[2];
#pragma unroll
            for (int mi = 0; mi < 4; mi++) {
                const uint32_t a = st + ((wm * 4 + mi) * 2 + kk) * 512 + lane * 16;
                ah[mi] = lds128(a);
                al[mi] = lds128(a + 8192);
            }
#pragma unroll
            for (int nb = 0; nb < 2; nb++) {
                const uint32_t a = st + 16384 + ((wn * 2 + nb) * 2 + kk) * 512 + lane * 16;
                bh[nb] = lds128(a);
                bl[nb] = lds128(a + 8192);
            }
#pragma unroll
            for (int mi = 0; mi < 4; mi++)
#pragma unroll
                for (int nb = 0; nb < 2; nb++) {
                    uint32_t bh0[2] = {bh[nb].x, bh[nb].z};
                    uint32_t bl0[2] = {bl[nb].x, bl[nb].z};
                    uint32_t bh1[2] = {bh[nb].y, bh[nb].w};
                    uint32_t bl1[2] = {bl[nb].y, bl[nb].w};
                    float* a0 = acc[mi][nb * 2];
                    float* a1 = acc[mi][nb * 2 + 1];
                    mma_tf32(a0, (const uint32_t*)&ah[mi], bh0);
                    mma_tf32(a0, (const uint32_t*)&al[mi], bh0);
                    mma_tf32(a0, (const uint32_t*)&ah[mi], bl0);
                    mma_tf32(a1, (const uint32_t*)&ah[mi], bh1);
                    mma_tf32(a1, (const uint32_t*)&al[mi], bh1);
                    mma_tf32(a1, (const uint32_t*)&ah[mi], bl1);
                }
        }
        __syncthreads();
    }

    // epilogue
#pragma unroll
    for (int mi = 0; mi < 4; mi++) {
        const int r = ci0 + wm * 64 + mi * 16 + grp;
#pragma unroll
        for (int nj = 0; nj < 4; nj++) {
            const int c = cj0 + wn * 32 + (nj >> 1) * 16 + (nj & 1) * 8 + 2 * qid;
            const float v0 = acc[mi][nj][0], v1 = acc[mi][nj][1];
            const float v2 = acc[mi][nj][2], v3 = acc[mi][nj][3];
            if (sym) {
                uint32_t h, l;
                split_tf32(v0, h, l);
                pack_store(oHi, oLo, c,     r,     96, h, l);
                pack_store(oHi, oLo, r,     c,     96, h, l);
                split_tf32(v1, h, l);
                pack_store(oHi, oLo, c + 1, r,     96, h, l);
                pack_store(oHi, oLo, r,     c + 1, 96, h, l);
                split_tf32(v2, h, l);
                pack_store(oHi, oLo, c,     r + 8, 96, h, l);
                pack_store(oHi, oLo, r + 8, c,     96, h, l);
                split_tf32(v3, h, l);
                pack_store(oHi, oLo, c + 1, r + 8, 96, h, l);
                pack_store(oHi, oLo, r + 8, c + 1, 96, h, l);
            } else {
                *(float2*)&oF[(long long)r * DIMC + c] = make_float2(v0, v1);
                *(float2*)&oF[(long long)(r + 8) * DIMC + c] = make_float2(v2, v3);
            }
        }
    }
}

// ---------------------------------------------------------------------------
// Per (m,b,h): L[d][e] = SCALE * sum_c U[h*64+d][c] * W[c][768+h*64+e]
// then column-wise (over d) softmax -> g_ctx[m][b][h]
// ---------------------------------------------------------------------------
__global__ __launch_bounds__(256) void ctx_kernel(
    const float* __restrict__ Wrgb, const float* __restrict__ Wdepth)
{
    __shared__ float Us[64][68];
    __shared__ float Ws[64][68];

    const int z = blockIdx.y;
    const int m = z >> 4, b = z & 15;
    const int h = blockIdx.x;
    const float* U = &g_U[m][b][0] + (long long)(h * 64) * DIMC;
    const float* W = (m == 0 ? Wrgb : Wdepth) + DIMC + h * 64;

    const int tid = threadIdx.x;
    const int ty = tid >> 4, tx = tid & 15;

    float acc[4][4];
#pragma unroll
    for (int i = 0; i < 4; i++)
#pragma unroll
        for (int j = 0; j < 4; j++) acc[i][j] = 0.f;

    for (int c0 = 0; c0 < DIMC; c0 += 64) {
#pragma unroll
        for (int t = 0; t < 4; t++) {
            const int f4 = tid + t * 256;
            const int r = f4 >> 4;
            const int cg = (f4 & 15) << 2;
            float4 u = *(const float4*)(U + (long long)r * DIMC + c0 + cg);
            Us[r][cg + 0] = u.x; Us[r][cg + 1] = u.y; Us[r][cg + 2] = u.z; Us[r][cg + 3] = u.w;
            float4 w = *(const float4*)(W + (long long)(c0 + r) * (2 * DIMC) + cg);
            Ws[r][cg + 0] = w.x; Ws[r][cg + 1] = w.y; Ws[r][cg + 2] = w.z; Ws[r][cg + 3] = w.w;
        }
        __syncthreads();
#pragma unroll 8
        for (int c = 0; c < 64; c++) {
            float u0 = Us[ty * 4 + 0][c], u1 = Us[ty * 4 + 1][c];
            float u2 = Us[ty * 4 + 2][c], u3 = Us[ty * 4 + 3][c];
            float w0 = Ws[c][tx * 4 + 0], w1 = Ws[c][tx * 4 + 1];
            float w2 = Ws[c][tx * 4 + 2], w3 = Ws[c][tx * 4 + 3];
            acc[0][0] += u0 * w0; acc[0][1] += u0 * w1; acc[0][2] += u0 * w2; acc[0][3] += u0 * w3;
            acc[1][0] += u1 * w0; acc[1][1] += u1 * w1; acc[1][2] += u1 * w2; acc[1][3] += u1 * w3;
            acc[2][0] += u2 * w0; acc[2][1] += u2 * w1; acc[2][2] += u2 * w2; acc[2][3] += u2 * w3;
            acc[3][0] += u3 * w0; acc[3][1] += u3 * w1; acc[3][2] += u3 * w2; acc[3][3] += u3 * w3;
        }
        __syncthreads();
    }

    const float SCALE = 0.125f;
#pragma unroll
    for (int i = 0; i < 4; i++)
#pragma unroll
        for (int j = 0; j < 4; j++)
            Us[ty * 4 + i][tx * 4 + j] = acc[i][j] * SCALE;
    __syncthreads();

    if (tid < 64) {
        const int e = tid;
        float mx = -1e30f;
#pragma unroll 8
        for (int d = 0; d < 64; d++) mx = fmaxf(mx, Us[d][e]);
        float s = 0.f;
#pragma unroll 8
        for (int d = 0; d < 64; d++) {
            float v = expf(Us[d][e] - mx);
            Us[d][e] = v;
            s += v;
        }
        const float inv = 1.f / s;
        float* cx = &g_ctx[m][b][h][0];
#pragma unroll 8
        for (int d = 0; d < 64; d++) cx[d * 64 + e] = Us[d][e] * inv;
    }
}

// ---------------------------------------------------------------------------
// out_m[b, n, h*64+e] = sum_d X_m[b, n, h*64+d] * ctx_{1-m}[b][h][d][e]
// ---------------------------------------------------------------------------
__global__ __launch_bounds__(256) void out_kernel(
    const float* __restrict__ rgb, const float* __restrict__ depth,
    float* __restrict__ out)
{
    __shared__ uint32_t As[64][68];
    __shared__ uint32_t Bs[64][68];

    const int z = blockIdx.z;
    const int m = z >> 4, b = z & 15;
    const int h = blockIdx.y;
    const int n0 = blockIdx.x * 64;

    const float* X = (m == 0 ? rgb : depth) + ((long long)b * NTOK + n0) * DIMC + h * HD;
    const float* cx = &g_ctx[1 - m][b][h][0];
    float* O = out + (long long)m * BATCH * NTOK * DIMC + ((long long)b * NTOK + n0) * DIMC + h * HD;

    const int tid = threadIdx.x;
    const int wid = tid >> 5, lane = tid & 31;
    const int wm = wid >> 2, wn = wid & 3;
    const int grp = lane >> 2, qid = lane & 3;

#pragma unroll
    for (int t = 0; t < 4; t++) {
        const int f4 = tid + t * 256;
        const int r = f4 >> 4;
        const int cg = (f4 & 15) << 2;
        float4 v = *(const float4*)(X + (long long)r * DIMC + cg);
        As[r][cg + 0] = to_tf32(v.x); As[r][cg + 1] = to_tf32(v.y);
        As[r][cg + 2] = to_tf32(v.z); As[r][cg + 3] = to_tf32(v.w);
    }
#pragma unroll
    for (int t = 0; t < 4; t++) {
        const int f4 = tid + t * 256;
        const int d = f4 >> 4;
        const int eg = (f4 & 15) << 2;
        float4 v = *(const float4*)(cx + d * 64 + eg);
        Bs[eg + 0][d] = to_tf32(v.x); Bs[eg + 1][d] = to_tf32(v.y);
        Bs[eg + 2][d] = to_tf32(v.z); Bs[eg + 3][d] = to_tf32(v.w);
    }
    __syncthreads();

    float acc[2][2][4];
#pragma unroll
    for (int a = 0; a < 2; a++)
#pragma unroll
        for (int c = 0; c < 2; c++)
#pragma unroll
            for (int r = 0; r < 4; r++) acc[a][c][r] = 0.f;

#pragma unroll
    for (int ks = 0; ks < 8; ks++) {
        const int kq = (ks << 3) + qid;
        uint32_t ah[2][4], bh[2][2];
#pragma unroll
        for (int mi = 0; mi < 2; mi++) {
            const int i = wm * 32 + mi * 16 + grp;
            ah[mi][0] = As[i][kq];     ah[mi][1] = As[i + 8][kq];
            ah[mi][2] = As[i][kq + 4]; ah[mi][3] = As[i + 8][kq + 4];
        }
#pragma unroll
        for (int nj = 0; nj < 2; nj++) {
            const int n = wn * 16 + nj * 8 + grp;
            bh[nj][0] = Bs[n][kq]; bh[nj][1] = Bs[n][kq + 4];
        }
#pragma unroll
        for (int mi = 0; mi < 2; mi++)
#pragma unroll
            for (int nj = 0; nj < 2; nj++)
                mma_tf32(acc[mi][nj], ah[mi], bh[nj]);
    }

#pragma unroll
    for (int mi = 0; mi < 2; mi++) {
        const int r0 = wm * 32 + mi * 16 + grp;
#pragma unroll
        for (int nj = 0; nj < 2; nj++) {
            const int c0c = wn * 16 + nj * 8 + 2 * qid;
            *(float2*)(O + (long long)r0 * DIMC + c0c) =
                make_float2(acc[mi][nj][0], acc[mi][nj][1]);
            *(float2*)(O + (long long)(r0 + 8) * DIMC + c0c) =
                make_float2(acc[mi][nj][2], acc[mi][nj][3]);
        }
    }
}

// ---------------------------------------------------------------------------
extern "C" void kernel_launch(void* const* d_in, const int* in_sizes, int n_in,
                              void* d_out, int out_size)
{
    const float* rgb = (const float*)d_in[0];
    const float* dep = (const float*)d_in[1];
    const float* Wr  = (const float*)d_in[2];
    const float* Wd  = (const float*)d_in[3];
    float* out = (float*)d_out;

    uint32_t *pXhi, *pXlo, *pWhi, *pWlo, *pGhi, *pGlo;
    float *pU;
    cudaGetSymbolAddress((void**)&pXhi, g_Xphi);
    cudaGetSymbolAddress((void**)&pXlo, g_Xplo);
    cudaGetSymbolAddress((void**)&pWhi, g_Wphi);
    cudaGetSymbolAddress((void**)&pWlo, g_Wplo);
    cudaGetSymbolAddress((void**)&pGhi, g_Gphi);
    cudaGetSymbolAddress((void**)&pGlo, g_Gplo);
    cudaGetSymbolAddress((void**)&pU, g_U);

    cudaFuncSetAttribute(gemm_tc_kernel,
                         cudaFuncAttributeMaxDynamicSharedMemorySize, GEMM_SMEM);

    const long long XS = (long long)NTOK * DIMC;   // per-batch X elems (src)
    const long long XP = (long long)DIMC * NTOK;   // per-batch pack elems
    const long long GB = (long long)DIMC * DIMC;
    const long long WB = (long long)DIMC * DIMC;

    // pre-pass: pack + split
    pack_split_kernel<<<dim3(12, 64, 16), 256>>>(rgb, XS, DIMC, NTOK, pXhi, pXlo, XP);
    pack_split_kernel<<<dim3(12, 64, 16), 256>>>(dep, XS, DIMC, NTOK,
                                                 pXhi + 16 * XP, pXlo + 16 * XP, XP);
    pack_split_kernel<<<dim3(12, 12, 1), 256>>>(Wr, 0, 2 * DIMC, DIMC, pWhi, pWlo, 0);
    pack_split_kernel<<<dim3(12, 12, 1), 256>>>(Wd, 0, 2 * DIMC, DIMC,
                                                pWhi + WB, pWlo + WB, 0);

    // G = XᵀX (symmetric, 21 tiles), epilogue writes packed split G
    gemm_tc_kernel<<<dim3(21, 16), 256, GEMM_SMEM>>>(
        pXhi, pXlo, XP, pXhi, pXlo, XP, NTOK, 1, pGhi, pGlo, nullptr, GB);
    gemm_tc_kernel<<<dim3(21, 16), 256, GEMM_SMEM>>>(
        pXhi + 16 * XP, pXlo + 16 * XP, XP, pXhi + 16 * XP, pXlo + 16 * XP, XP,
        NTOK, 1, pGhi + 16 * GB, pGlo + 16 * GB, nullptr, GB);

    // U = Wkᵀ G, epilogue writes f32 U
    gemm_tc_kernel<<<dim3(36, 16), 256, GEMM_SMEM>>>(
        pWhi, pWlo, 0, pGhi, pGlo, GB, DIMC, 0, nullptr, nullptr, pU, GB);
    gemm_tc_kernel<<<dim3(36, 16), 256, GEMM_SMEM>>>(
        pWhi + WB, pWlo + WB, 0, pGhi + 16 * GB, pGlo + 16 * GB, GB,
        DIMC, 0, nullptr, nullptr, pU + 16 * GB, GB);

    // per-head logits + softmax -> ctx
    ctx_kernel<<<dim3(NHEADS, 32), 256>>>(Wr, Wd);

    // out = X @ blockdiag(ctx_other)
    out_kernel<<<dim3(NTOK / 64, NHEADS, 32), 256>>>(rgb, dep, out);
}

// round 5
// speedup vs baseline: 2.3103x; 1.6239x over previous
#include <cuda_runtime.h>
#include <cuda_bf16.h>
#include <cstdint>

// ---------------------------------------------------------------------------
// KTBCrossAttention restructured (mma.sync, f32-packed operands, split-in-reg):
//   Xp   = pack(Xᵀ) f32, fragment-ordered (pre-pass)
//   G_mb = XᵀX   (768x768, K=4096, sym)  [3xTF32 mma.sync, split after LDS]
//   U_mb = WkᵀG  (768x768, K=768)
//   ctx  = softmax_d( s * U[h] @ Wv_h )
//   out  = X @ blockdiag(ctx_other)
//
// Pack layout for M[R][K]: block = (r>>4)*(K>>3)+(k>>3), 128 elems/block,
//   within: lane=(r&7)*4+(k&3), reg=((r>>3)&1)+2*((k>>2)&1).
// One LDS.128 per lane = A-frag(16x8); B-frags of the two 8-col halves of a
// 16-row block come from the same LDS.128 via regs {x,z} / {y,w}.
// hi/lo tf32 split happens in registers AFTER the LDS (halves all traffic).
// ---------------------------------------------------------------------------

#define DIMC 768
#define NTOK 4096
#define BATCH 16
#define NHEADS 12
#define HD 64

#define KB 16
#define STAGES 4
#define STAGE_BYTES 16384
#define GEMM_SMEM (STAGES * STAGE_BYTES)   // 64 KB

// scratch (device globals; allocation-free contract)
__device__ float g_Xp[2][BATCH][DIMC * NTOK];        // 402.6 MB
__device__ float g_Wp[2][DIMC * DIMC];               // 4.7 MB
__device__ float g_Gp[2][BATCH][DIMC * DIMC];        // 75.5 MB (packed f32)
__device__ float g_U[2][BATCH][DIMC * DIMC];         // 75.5 MB (row-major)
__device__ float g_ctx[2][BATCH][NHEADS][HD * HD];   // 6.3 MB

// ---------------------------------------------------------------------------
__device__ __forceinline__ uint32_t smem_to_u32(const void* p) {
    uint32_t a;
    asm("{ .reg .u64 tmp; cvta.to.shared.u64 tmp, %1; cvt.u32.u64 %0, tmp; }"
        : "=r"(a) : "l"(p));
    return a;
}

__device__ __forceinline__ void cp16(uint32_t saddr, const void* g) {
    asm volatile("cp.async.cg.shared.global [%0], [%1], 16;" :: "r"(saddr), "l"(g));
}
#define CP_COMMIT() asm volatile("cp.async.commit_group;" ::: "memory")
#define CP_WAIT(n)  asm volatile("cp.async.wait_group %0;" :: "n"(n) : "memory")

__device__ __forceinline__ uint4 lds128(uint32_t a) {
    uint4 v;
    asm volatile("ld.shared.v4.b32 {%0,%1,%2,%3}, [%4];"
                 : "=r"(v.x), "=r"(v.y), "=r"(v.z), "=r"(v.w) : "r"(a));
    return v;
}

__device__ __forceinline__ void mma_tf32(float* d, const uint32_t* a, const uint32_t* b) {
    asm volatile(
        "mma.sync.aligned.m16n8k8.row.col.f32.tf32.tf32.f32 "
        "{%0,%1,%2,%3}, {%4,%5,%6,%7}, {%8,%9}, {%0,%1,%2,%3};"
        : "+f"(d[0]), "+f"(d[1]), "+f"(d[2]), "+f"(d[3])
        : "r"(a[0]), "r"(a[1]), "r"(a[2]), "r"(a[3]), "r"(b[0]), "r"(b[1]));
}

__device__ __forceinline__ void split1(uint32_t f, uint32_t& hi, uint32_t& lo) {
    float v = __uint_as_float(f);
    asm("cvt.rna.tf32.f32 %0, %1;" : "=r"(hi) : "f"(v));
    float r = v - __uint_as_float(hi);
    asm("cvt.rna.tf32.f32 %0, %1;" : "=r"(lo) : "f"(r));
}

__device__ __forceinline__ void split4(uint4 f, uint4& hi, uint4& lo) {
    split1(f.x, hi.x, lo.x);
    split1(f.y, hi.y, lo.y);
    split1(f.z, hi.z, lo.z);
    split1(f.w, hi.w, lo.w);
}

__device__ __forceinline__ uint32_t to_tf32(float v) {
    uint32_t t;
    asm("cvt.rna.tf32.f32 %0, %1;" : "=r"(t) : "f"(v));
    return t;
}

__device__ __forceinline__ void pack_store_f32(float* __restrict__ o,
                                               int r_, int k_, int Kb, float v) {
    long long off = (long long)((r_ >> 4) * Kb + (k_ >> 3)) * 128
                  + ((r_ & 7) * 4 + (k_ & 3)) * 4
                  + ((r_ >> 3) & 1) + 2 * ((k_ >> 2) & 1);
    o[off] = v;
}

// ---------------------------------------------------------------------------
// Pre-pass: read src[k][r] (row stride srcLd), transpose via smem, write f32
// fragment-packed array (coalesced). Tile = 64r x 64k.
// ---------------------------------------------------------------------------
__global__ __launch_bounds__(256) void pack_f32_kernel(
    const float* __restrict__ src, long long srcBStr, int srcLd, int K,
    float* __restrict__ oP, long long dstBStr)
{
    __shared__ float t[64][65];
    const int b = blockIdx.z;
    src += (long long)b * srcBStr;
    oP  += (long long)b * dstBStr;

    const int r0 = blockIdx.x * 64, k0 = blockIdx.y * 64;
    const int tid = threadIdx.x;
    const int Kb = K >> 3;

#pragma unroll
    for (int it = 0; it < 16; it++) {
        const int row = it * 4 + (tid >> 6);   // k-local
        const int col = tid & 63;              // r-local
        t[row][col] = src[(long long)(k0 + row) * srcLd + r0 + col];
    }
    __syncthreads();

#pragma unroll
    for (int it = 0; it < 16; it++) {
        const int e = it * 256 + tid;     // 4096 elems per tile
        const int w = e & 127;
        const int blk = e >> 7;
        const int mb = blk >> 3, kb = blk & 7;
        const int lane = w >> 2, reg = w & 3;
        const int rr = mb * 16 + (lane >> 2) + 8 * (reg & 1);
        const int kk = kb * 8 + (lane & 3) + 4 * ((reg >> 1) & 1);
        const long long gidx =
            (long long)(((r0 >> 4) + mb) * Kb + (k0 >> 3) + kb) * 128 + w;
        oP[gidx] = t[kk][rr];
    }
}

// ---------------------------------------------------------------------------
// GEMM C = AᵀB, operands fragment-packed f32, 128x128 CTA tile, KB=16 slab,
// 4-stage cp.async pipeline, hi/lo split in registers, 3xTF32 mma.sync.
// sym=1: triangular tiles of G; epilogue writes f32 pack (both mirrors).
// sym=0: full 6x6 tiles; epilogue writes row-major f32 (U).
// ---------------------------------------------------------------------------
__global__ __launch_bounds__(256, 2) void gemm_tc_kernel(
    const float* __restrict__ A, long long aBStr,
    const float* __restrict__ B, long long bBStr,
    int K, int sym,
    float* __restrict__ oP,
    float* __restrict__ oF, long long oBStr)
{
    extern __shared__ char smem[];
    const uint32_t smem_base = smem_to_u32(smem);
    const int tid = threadIdx.x;
    const int wid = tid >> 5, lane = tid & 31;
    const int wm = wid >> 2, wn = wid & 3;
    const int grp = lane >> 2, qid = lane & 3;
    const int z = blockIdx.y;

    A += z * aBStr;
    B += z * bBStr;
    if (oP) oP += z * oBStr;
    if (oF) oF += z * oBStr;

    int ti, tj;
    if (sym) {
        int rem = blockIdx.x;
        ti = 0;
        while (rem >= 6 - ti) { rem -= (6 - ti); ti++; }
        tj = ti + rem;
    } else {
        ti = blockIdx.x / 6;
        tj = blockIdx.x % 6;
    }
    const int ci0 = ti * 128, cj0 = tj * 128;
    const int Kb = K >> 3;
    const int NS = K / KB;

    // copy roles: 128 threads per operand; thread covers 4 consecutive uint4
    const int q = tid >> 7, t7 = tid & 127;
    const int mb = t7 >> 4, i4 = t7 & 15;
    const float* gq = q ? B : A;
    const int rowblk0 = (q ? cj0 : ci0) >> 4;
    const float* gsrc = gq + (long long)(rowblk0 + mb) * Kb * 128 + i4 * 16;
    const uint32_t sdst0 = smem_base + q * 8192 + mb * 1024 + i4 * 64;

    float acc[4][4][4];
#pragma unroll
    for (int a = 0; a < 4; a++)
#pragma unroll
        for (int b = 0; b < 4; b++)
#pragma unroll
            for (int c = 0; c < 4; c++) acc[a][b][c] = 0.f;

    // prologue: stages 0..2
#pragma unroll
    for (int s = 0; s < STAGES - 1; s++) {
        const float* g = gsrc + (long long)s * 256;
        const uint32_t d = sdst0 + s * STAGE_BYTES;
#pragma unroll
        for (int i = 0; i < 4; i++) cp16(d + i * 16, g + i * 4);
        CP_COMMIT();
    }

    for (int s = 0; s < NS; s++) {
        if (s + STAGES - 1 < NS) {
            const int sp = s + STAGES - 1;
            const float* g = gsrc + (long long)sp * 256;
            const uint32_t d = sdst0 + (sp & (STAGES - 1)) * STAGE_BYTES;
#pragma unroll
            for (int i = 0; i < 4; i++) cp16(d + i * 16, g + i * 4);
        }
        CP_COMMIT();
        CP_WAIT(STAGES - 1);
        __syncthreads();

        const uint32_t st = smem_base + (s & (STAGES - 1)) * STAGE_BYTES;
#pragma unroll
        for (int kk = 0; kk < 2; kk++) {
            // B fragments: 2 LDS.128, split in regs
            uint4 bh[2], bl[2];
#pragma unroll
            for (int nb = 0; nb < 2; nb++) {
                uint4 bf = lds128(st + 8192 + ((wn * 2 + nb) * 2 + kk) * 512 + lane * 16);
                split4(bf, bh[nb], bl[nb]);
            }
#pragma unroll
            for (int mi = 0; mi < 4; mi++) {
                uint4 af = lds128(st + ((wm * 4 + mi) * 2 + kk) * 512 + lane * 16);
                uint4 ah, al;
                split4(af, ah, al);
#pragma unroll
                for (int nb = 0; nb < 2; nb++) {
                    uint32_t bh0[2] = {bh[nb].x, bh[nb].z};
                    uint32_t bl0[2] = {bl[nb].x, bl[nb].z};
                    uint32_t bh1[2] = {bh[nb].y, bh[nb].w};
                    uint32_t bl1[2] = {bl[nb].y, bl[nb].w};
                    float* a0 = acc[mi][nb * 2];
                    float* a1 = acc[mi][nb * 2 + 1];
                    mma_tf32(a0, (const uint32_t*)&ah, bh0);
                    mma_tf32(a0, (const uint32_t*)&al, bh0);
                    mma_tf32(a0, (const uint32_t*)&ah, bl0);
                    mma_tf32(a1, (const uint32_t*)&ah, bh1);
                    mma_tf32(a1, (const uint32_t*)&al, bh1);
                    mma_tf32(a1, (const uint32_t*)&ah, bl1);
                }
            }
        }
        __syncthreads();
    }

    // epilogue
#pragma unroll
    for (int mi = 0; mi < 4; mi++) {
        const int r = ci0 + wm * 64 + mi * 16 + grp;
#pragma unroll
        for (int nj = 0; nj < 4; nj++) {
            const int c = cj0 + wn * 32 + (nj >> 1) * 16 + (nj & 1) * 8 + 2 * qid;
            const float v0 = acc[mi][nj][0], v1 = acc[mi][nj][1];
            const float v2 = acc[mi][nj][2], v3 = acc[mi][nj][3];
            if (sym) {
                pack_store_f32(oP, c,     r,     96, v0);
                pack_store_f32(oP, r,     c,     96, v0);
                pack_store_f32(oP, c + 1, r,     96, v1);
                pack_store_f32(oP, r,     c + 1, 96, v1);
                pack_store_f32(oP, c,     r + 8, 96, v2);
                pack_store_f32(oP, r + 8, c,     96, v2);
                pack_store_f32(oP, c + 1, r + 8, 96, v3);
                pack_store_f32(oP, r + 8, c + 1, 96, v3);
            } else {
                *(float2*)&oF[(long long)r * DIMC + c] = make_float2(v0, v1);
                *(float2*)&oF[(long long)(r + 8) * DIMC + c] = make_float2(v2, v3);
            }
        }
    }
}

// ---------------------------------------------------------------------------
// Per (m,b,h): L[d][e] = SCALE * sum_c U[h*64+d][c] * W[c][768+h*64+e]
// then column-wise (over d) softmax -> g_ctx[m][b][h]
// ---------------------------------------------------------------------------
__global__ __launch_bounds__(256) void ctx_kernel(
    const float* __restrict__ Wrgb, const float* __restrict__ Wdepth)
{
    __shared__ float Us[64][68];
    __shared__ float Ws[64][68];

    const int z = blockIdx.y;
    const int m = z >> 4, b = z & 15;
    const int h = blockIdx.x;
    const float* U = &g_U[m][b][0] + (long long)(h * 64) * DIMC;
    const float* W = (m == 0 ? Wrgb : Wdepth) + DIMC + h * 64;

    const int tid = threadIdx.x;
    const int ty = tid >> 4, tx = tid & 15;

    float acc[4][4];
#pragma unroll
    for (int i = 0; i < 4; i++)
#pragma unroll
        for (int j = 0; j < 4; j++) acc[i][j] = 0.f;

    for (int c0 = 0; c0 < DIMC; c0 += 64) {
#pragma unroll
        for (int t = 0; t < 4; t++) {
            const int f4 = tid + t * 256;
            const int r = f4 >> 4;
            const int cg = (f4 & 15) << 2;
            float4 u = *(const float4*)(U + (long long)r * DIMC + c0 + cg);
            Us[r][cg + 0] = u.x; Us[r][cg + 1] = u.y; Us[r][cg + 2] = u.z; Us[r][cg + 3] = u.w;
            float4 w = *(const float4*)(W + (long long)(c0 + r) * (2 * DIMC) + cg);
            Ws[r][cg + 0] = w.x; Ws[r][cg + 1] = w.y; Ws[r][cg + 2] = w.z; Ws[r][cg + 3] = w.w;
        }
        __syncthreads();
#pragma unroll 8
        for (int c = 0; c < 64; c++) {
            float u0 = Us[ty * 4 + 0][c], u1 = Us[ty * 4 + 1][c];
            float u2 = Us[ty * 4 + 2][c], u3 = Us[ty * 4 + 3][c];
            float w0 = Ws[c][tx * 4 + 0], w1 = Ws[c][tx * 4 + 1];
            float w2 = Ws[c][tx * 4 + 2], w3 = Ws[c][tx * 4 + 3];
            acc[0][0] += u0 * w0; acc[0][1] += u0 * w1; acc[0][2] += u0 * w2; acc[0][3] += u0 * w3;
            acc[1][0] += u1 * w0; acc[1][1] += u1 * w1; acc[1][2] += u1 * w2; acc[1][3] += u1 * w3;
            acc[2][0] += u2 * w0; acc[2][1] += u2 * w1; acc[2][2] += u2 * w2; acc[2][3] += u2 * w3;
            acc[3][0] += u3 * w0; acc[3][1] += u3 * w1; acc[3][2] += u3 * w2; acc[3][3] += u3 * w3;
        }
        __syncthreads();
    }

    const float SCALE = 0.125f;
#pragma unroll
    for (int i = 0; i < 4; i++)
#pragma unroll
        for (int j = 0; j < 4; j++)
            Us[ty * 4 + i][tx * 4 + j] = acc[i][j] * SCALE;
    __syncthreads();

    if (tid < 64) {
        const int e = tid;
        float mx = -1e30f;
#pragma unroll 8
        for (int d = 0; d < 64; d++) mx = fmaxf(mx, Us[d][e]);
        float s = 0.f;
#pragma unroll 8
        for (int d = 0; d < 64; d++) {
            float v = expf(Us[d][e] - mx);
            Us[d][e] = v;
            s += v;
        }
        const float inv = 1.f / s;
        float* cx = &g_ctx[m][b][h][0];
#pragma unroll 8
        for (int d = 0; d < 64; d++) cx[d * 64 + e] = Us[d][e] * inv;
    }
}

// ---------------------------------------------------------------------------
// out_m[b, n, h*64+e] = sum_d X_m[b, n, h*64+d] * ctx_{1-m}[b][h][d][e]
// ---------------------------------------------------------------------------
__global__ __launch_bounds__(256) void out_kernel(
    const float* __restrict__ rgb, const float* __restrict__ depth,
    float* __restrict__ out)
{
    __shared__ uint32_t As[64][68];
    __shared__ uint32_t Bs[64][68];

    const int z = blockIdx.z;
    const int m = z >> 4, b = z & 15;
    const int h = blockIdx.y;
    const int n0 = blockIdx.x * 64;

    const float* X = (m == 0 ? rgb : depth) + ((long long)b * NTOK + n0) * DIMC + h * HD;
    const float* cx = &g_ctx[1 - m][b][h][0];
    float* O = out + (long long)m * BATCH * NTOK * DIMC + ((long long)b * NTOK + n0) * DIMC + h * HD;

    const int tid = threadIdx.x;
    const int wid = tid >> 5, lane = tid & 31;
    const int wm = wid >> 2, wn = wid & 3;
    const int grp = lane >> 2, qid = lane & 3;

#pragma unroll
    for (int t = 0; t < 4; t++) {
        const int f4 = tid + t * 256;
        const int r = f4 >> 4;
        const int cg = (f4 & 15) << 2;
        float4 v = *(const float4*)(X + (long long)r * DIMC + cg);
        As[r][cg + 0] = to_tf32(v.x); As[r][cg + 1] = to_tf32(v.y);
        As[r][cg + 2] = to_tf32(v.z); As[r][cg + 3] = to_tf32(v.w);
    }
#pragma unroll
    for (int t = 0; t < 4; t++) {
        const int f4 = tid + t * 256;
        const int d = f4 >> 4;
        const int eg = (f4 & 15) << 2;
        float4 v = *(const float4*)(cx + d * 64 + eg);
        Bs[eg + 0][d] = to_tf32(v.x); Bs[eg + 1][d] = to_tf32(v.y);
        Bs[eg + 2][d] = to_tf32(v.z); Bs[eg + 3][d] = to_tf32(v.w);
    }
    __syncthreads();

    float acc[2][2][4];
#pragma unroll
    for (int a = 0; a < 2; a++)
#pragma unroll
        for (int c = 0; c < 2; c++)
#pragma unroll
            for (int r = 0; r < 4; r++) acc[a][c][r] = 0.f;

#pragma unroll
    for (int ks = 0; ks < 8; ks++) {
        const int kq = (ks << 3) + qid;
        uint32_t ah[2][4], bh[2][2];
#pragma unroll
        for (int mi = 0; mi < 2; mi++) {
            const int i = wm * 32 + mi * 16 + grp;
            ah[mi][0] = As[i][kq];     ah[mi][1] = As[i + 8][kq];
            ah[mi][2] = As[i][kq + 4]; ah[mi][3] = As[i + 8][kq + 4];
        }
#pragma unroll
        for (int nj = 0; nj < 2; nj++) {
            const int n = wn * 16 + nj * 8 + grp;
            bh[nj][0] = Bs[n][kq]; bh[nj][1] = Bs[n][kq + 4];
        }
#pragma unroll
        for (int mi = 0; mi < 2; mi++)
#pragma unroll
            for (int nj = 0; nj < 2; nj++)
                mma_tf32(acc[mi][nj], ah[mi], bh[nj]);
    }

#pragma unroll
    for (int mi = 0; mi < 2; mi++) {
        const int r0 = wm * 32 + mi * 16 + grp;
#pragma unroll
        for (int nj = 0; nj < 2; nj++) {
            const int c0c = wn * 16 + nj * 8 + 2 * qid;
            *(float2*)(O + (long long)r0 * DIMC + c0c) =
                make_float2(acc[mi][nj][0], acc[mi][nj][1]);
            *(float2*)(O + (long long)(r0 + 8) * DIMC + c0c) =
                make_float2(acc[mi][nj][2], acc[mi][nj][3]);
        }
    }
}

// ---------------------------------------------------------------------------
extern "C" void kernel_launch(void* const* d_in, const int* in_sizes, int n_in,
                              void* d_out, int out_size)
{
    const float* rgb = (const float*)d_in[0];
    const float* dep = (const float*)d_in[1];
    const float* Wr  = (const float*)d_in[2];
    const float* Wd  = (const float*)d_in[3];
    float* out = (float*)d_out;

    float *pX, *pW, *pG, *pU;
    cudaGetSymbolAddress((void**)&pX, g_Xp);
    cudaGetSymbolAddress((void**)&pW, g_Wp);
    cudaGetSymbolAddress((void**)&pG, g_Gp);
    cudaGetSymbolAddress((void**)&pU, g_U);

    cudaFuncSetAttribute(gemm_tc_kernel,
                         cudaFuncAttributeMaxDynamicSharedMemorySize, GEMM_SMEM);

    const long long XS = (long long)NTOK * DIMC;   // per-batch X elems (src)
    const long long XP = (long long)DIMC * NTOK;   // per-batch pack elems
    const long long GB = (long long)DIMC * DIMC;
    const long long WB = (long long)DIMC * DIMC;

    // pre-pass: pack to fragment order (f32)
    pack_f32_kernel<<<dim3(12, 64, 16), 256>>>(rgb, XS, DIMC, NTOK, pX, XP);
    pack_f32_kernel<<<dim3(12, 64, 16), 256>>>(dep, XS, DIMC, NTOK, pX + 16 * XP, XP);
    pack_f32_kernel<<<dim3(12, 12, 1), 256>>>(Wr, 0, 2 * DIMC, DIMC, pW, 0);
    pack_f32_kernel<<<dim3(12, 12, 1), 256>>>(Wd, 0, 2 * DIMC, DIMC, pW + WB, 0);

    // G = XᵀX (symmetric, 21 tiles), epilogue writes packed f32 G
    gemm_tc_kernel<<<dim3(21, 16), 256, GEMM_SMEM>>>(
        pX, XP, pX, XP, NTOK, 1, pG, nullptr, GB);
    gemm_tc_kernel<<<dim3(21, 16), 256, GEMM_SMEM>>>(
        pX + 16 * XP, XP, pX + 16 * XP, XP, NTOK, 1, pG + 16 * GB, nullptr, GB);

    // U = Wkᵀ G (G symmetric -> packed G valid as B operand)
    gemm_tc_kernel<<<dim3(36, 16), 256, GEMM_SMEM>>>(
        pW, 0, pG, GB, DIMC, 0, nullptr, pU, GB);
    gemm_tc_kernel<<<dim3(36, 16), 256, GEMM_SMEM>>>(
        pW + WB, 0, pG + 16 * GB, GB, DIMC, 0, nullptr, pU + 16 * GB, GB);

    // per-head logits + softmax -> ctx
    ctx_kernel<<<dim3(NHEADS, 32), 256>>>(Wr, Wd);

    // out = X @ blockdiag(ctx_other)
    out_kernel<<<dim3(NTOK / 64, NHEADS, 32), 256>>>(rgb, dep, out);
}

// round 6
// speedup vs baseline: 3.6309x; 1.5716x over previous
#include <cuda_runtime.h>
#include <cuda_bf16.h>
#include <cstdint>

// ---------------------------------------------------------------------------
// KTBCrossAttention restructured (bf16x3 mma.sync, fragment-packed operands):
//   Xh/Xl = pack(split_bf16(Xᵀ))  fragment-ordered (pre-pass)
//   G_mb  = XᵀX   (768x768, K=4096, sym)  [3xBF16 m16n8k16 mma.sync]
//   U_mb  = WkᵀG  (768x768, K=768)        [3xBF16]
//   ctx   = softmax_d( s * U[h] @ Wv_h )
//   out   = X @ blockdiag(ctx_other)      [tf32 mma]
//
// Pack layout for M[R][K] as bf16 pairs (uint32 = 2 adjacent k):
//   block = (r>>4)*(K>>4) + (k>>4)    (16r x 16k block = 128 uint32)
//   within: lane = (r&7)*4 + ((k>>1)&3), reg = ((r>>3)&1) + 2*((k>>3)&1)
// One LDS.128 per lane = m16n8k16 A-frag. As B operand, the two 8-col halves
// of a 16-row block use regs {x,z} / {y,w} of the same LDS.128.
// hi and lo bf16 are separate arrays (hi+lo = 4B/elem, same traffic as f32).
// ---------------------------------------------------------------------------

#define DIMC 768
#define NTOK 4096
#define BATCH 16
#define NHEADS 12
#define HD 64

#define STAGES 4
#define STAGE_BYTES 16384
#define GEMM_SMEM (STAGES * STAGE_BYTES)   // 64 KB

// scratch (device globals; allocation-free contract)
__device__ uint32_t g_Xh[2][BATCH][DIMC * (NTOK / 2)];   // 201.3 MB
__device__ uint32_t g_Xl[2][BATCH][DIMC * (NTOK / 2)];   // 201.3 MB
__device__ uint32_t g_Wh[2][DIMC * (DIMC / 2)];          // 2.4 MB
__device__ uint32_t g_Wl[2][DIMC * (DIMC / 2)];
__device__ uint32_t g_Gh[2][BATCH][DIMC * (DIMC / 2)];   // 37.7 MB
__device__ uint32_t g_Gl[2][BATCH][DIMC * (DIMC / 2)];   // 37.7 MB
__device__ float    g_U[2][BATCH][DIMC * DIMC];          // 75.5 MB
__device__ float    g_ctx[2][BATCH][NHEADS][HD * HD];    // 6.3 MB

// ---------------------------------------------------------------------------
__device__ __forceinline__ uint32_t smem_to_u32(const void* p) {
    uint32_t a;
    asm("{ .reg .u64 tmp; cvta.to.shared.u64 tmp, %1; cvt.u32.u64 %0, tmp; }"
        : "=r"(a) : "l"(p));
    return a;
}

__device__ __forceinline__ void cp16(uint32_t saddr, const void* g) {
    asm volatile("cp.async.cg.shared.global [%0], [%1], 16;" :: "r"(saddr), "l"(g));
}
#define CP_COMMIT() asm volatile("cp.async.commit_group;" ::: "memory")
#define CP_WAIT(n)  asm volatile("cp.async.wait_group %0;" :: "n"(n) : "memory")

__device__ __forceinline__ uint4 lds128(uint32_t a) {
    uint4 v;
    asm volatile("ld.shared.v4.b32 {%0,%1,%2,%3}, [%4];"
                 : "=r"(v.x), "=r"(v.y), "=r"(v.z), "=r"(v.w) : "r"(a));
    return v;
}

__device__ __forceinline__ void mma_bf16(float* d, const uint32_t* a, const uint32_t* b) {
    asm volatile(
        "mma.sync.aligned.m16n8k16.row.col.f32.bf16.bf16.f32 "
        "{%0,%1,%2,%3}, {%4,%5,%6,%7}, {%8,%9}, {%0,%1,%2,%3};"
        : "+f"(d[0]), "+f"(d[1]), "+f"(d[2]), "+f"(d[3])
        : "r"(a[0]), "r"(a[1]), "r"(a[2]), "r"(a[3]), "r"(b[0]), "r"(b[1]));
}

__device__ __forceinline__ void mma_tf32(float* d, const uint32_t* a, const uint32_t* b) {
    asm volatile(
        "mma.sync.aligned.m16n8k8.row.col.f32.tf32.tf32.f32 "
        "{%0,%1,%2,%3}, {%4,%5,%6,%7}, {%8,%9}, {%0,%1,%2,%3};"
        : "+f"(d[0]), "+f"(d[1]), "+f"(d[2]), "+f"(d[3])
        : "r"(a[0]), "r"(a[1]), "r"(a[2]), "r"(a[3]), "r"(b[0]), "r"(b[1]));
}

__device__ __forceinline__ uint32_t to_tf32(float v) {
    uint32_t t;
    asm("cvt.rna.tf32.f32 %0, %1;" : "=r"(t) : "f"(v));
    return t;
}

// split two floats into packed bf16x2 hi / lo
__device__ __forceinline__ void split2_bf16(float a, float b,
                                            uint32_t& h, uint32_t& l) {
    __nv_bfloat16 ha = __float2bfloat16_rn(a);
    __nv_bfloat16 hb = __float2bfloat16_rn(b);
    float ra = a - __bfloat162float(ha);
    float rb = b - __bfloat162float(hb);
    __nv_bfloat16 la = __float2bfloat16_rn(ra);
    __nv_bfloat16 lb = __float2bfloat16_rn(rb);
    __nv_bfloat162 hp; hp.x = ha; hp.y = hb;
    __nv_bfloat162 lp; lp.x = la; lp.y = lb;
    h = *reinterpret_cast<uint32_t*>(&hp);
    l = *reinterpret_cast<uint32_t*>(&lp);
}

// ---------------------------------------------------------------------------
// Pre-pass: read src[k][r] (row stride srcLd), transpose via smem, bf16-split,
// write fragment-packed hi/lo arrays (coalesced). Tile = 64r x 64k.
// ---------------------------------------------------------------------------
__global__ __launch_bounds__(256) void pack_bf16_kernel(
    const float* __restrict__ src, long long srcBStr, int srcLd, int K,
    uint32_t* __restrict__ oH, uint32_t* __restrict__ oL, long long dstBStr)
{
    __shared__ float t[64][65];
    const int b = blockIdx.z;
    src += (long long)b * srcBStr;
    oH  += (long long)b * dstBStr;
    oL  += (long long)b * dstBStr;

    const int r0 = blockIdx.x * 64, k0 = blockIdx.y * 64;
    const int tid = threadIdx.x;
    const int Kb16 = K >> 4;

#pragma unroll
    for (int it = 0; it < 16; it++) {
        const int row = it * 4 + (tid >> 6);   // k-local
        const int col = tid & 63;              // r-local
        t[row][col] = src[(long long)(k0 + row) * srcLd + r0 + col];
    }
    __syncthreads();

#pragma unroll
    for (int it = 0; it < 8; it++) {
        const int e = it * 256 + tid;     // 2048 uint32 per tile
        const int w = e & 127;
        const int blk = e >> 7;           // 16 blocks (4 rb x 4 kb)
        const int mb = blk >> 2, kb = blk & 3;
        const int lane = w >> 2, reg = w & 3;
        const int rr = mb * 16 + (lane >> 2) + 8 * (reg & 1);
        const int kk = kb * 16 + ((lane & 3) + 4 * ((reg >> 1) & 1)) * 2;
        uint32_t h, l;
        split2_bf16(t[kk][rr], t[kk + 1][rr], h, l);
        const long long gidx =
            (long long)(((r0 >> 4) + mb) * Kb16 + (k0 >> 4) + kb) * 128 + w;
        oH[gidx] = h;
        oL[gidx] = l;
    }
}

// ---------------------------------------------------------------------------
// GEMM C[i][j] = sum_k A[i][k] B[j][k], operands fragment-packed bf16 hi/lo.
// 128x128 CTA tile, k16 slab, 4-stage cp.async pipeline, 3xBF16 mma.sync.
// sym=1: triangular tiles of G; epilogue stages via smem and writes bf16
//        fragment-packed G (direct + mirror, both STG.128-coalesced).
// sym=0: full 6x6 tiles; epilogue writes row-major f32 (U).
// ---------------------------------------------------------------------------
__global__ __launch_bounds__(256, 2) void gemm_bf16_kernel(
    const uint32_t* __restrict__ Ah, const uint32_t* __restrict__ Al,
    long long aBStr,
    const uint32_t* __restrict__ Bh, const uint32_t* __restrict__ Bl,
    long long bBStr,
    int K, int sym,
    uint32_t* __restrict__ oGh, uint32_t* __restrict__ oGl,
    float* __restrict__ oF, long long oBStr)
{
    extern __shared__ char smem[];
    const uint32_t smem_base = smem_to_u32(smem);
    const int tid = threadIdx.x;
    const int wid = tid >> 5, lane = tid & 31;
    const int wm = wid >> 2, wn = wid & 3;
    const int grp = lane >> 2, qid = lane & 3;
    const int z = blockIdx.y;

    Ah += z * aBStr; Al += z * aBStr;
    Bh += z * bBStr; Bl += z * bBStr;
    if (oGh) { oGh += z * oBStr; oGl += z * oBStr; }
    if (oF)  { oF  += z * oBStr; }

    int ti, tj;
    if (sym) {
        int rem = blockIdx.x;
        ti = 0;
        while (rem >= 6 - ti) { rem -= (6 - ti); ti++; }
        tj = ti + rem;
    } else {
        ti = blockIdx.x / 6;
        tj = blockIdx.x % 6;
    }
    const int ci0 = ti * 128, cj0 = tj * 128;
    const int Kb16 = K >> 4;
    const int NS = Kb16;

    // copy roles: quarter q in {Ah, Al, Bh, Bl}, 64 threads each.
    // Per slab each quarter moves 4KB: 8 rblocks x 128 uint32.
    const int q = tid >> 6, t6 = tid & 63;
    const int mb = t6 >> 3, i8 = t6 & 7;
    const uint32_t* gq = (q == 0) ? Ah : (q == 1) ? Al : (q == 2) ? Bh : Bl;
    const int rowblk0 = ((q < 2) ? ci0 : cj0) >> 4;
    const uint32_t* gsrc = gq + (long long)(rowblk0 + mb) * Kb16 * 128 + i8 * 16;
    const uint32_t sdst0 = smem_base + q * 4096 + mb * 512 + i8 * 64;

    float acc[4][4][4];
#pragma unroll
    for (int a = 0; a < 4; a++)
#pragma unroll
        for (int b = 0; b < 4; b++)
#pragma unroll
            for (int c = 0; c < 4; c++) acc[a][b][c] = 0.f;

    // prologue: stages 0..2
#pragma unroll
    for (int s = 0; s < STAGES - 1; s++) {
        const uint32_t* g = gsrc + (long long)s * 128;
        const uint32_t d = sdst0 + s * STAGE_BYTES;
#pragma unroll
        for (int i = 0; i < 4; i++) cp16(d + i * 16, g + i * 4);
        CP_COMMIT();
    }

    for (int s = 0; s < NS; s++) {
        if (s + STAGES - 1 < NS) {
            const int sp = s + STAGES - 1;
            const uint32_t* g = gsrc + (long long)sp * 128;
            const uint32_t d = sdst0 + (sp & (STAGES - 1)) * STAGE_BYTES;
#pragma unroll
            for (int i = 0; i < 4; i++) cp16(d + i * 16, g + i * 4);
        }
        CP_COMMIT();
        CP_WAIT(STAGES - 1);
        __syncthreads();

        const uint32_t st = smem_base + (s & (STAGES - 1)) * STAGE_BYTES;

        uint4 bhv[2], blv[2];
#pragma unroll
        for (int nb = 0; nb < 2; nb++) {
            bhv[nb] = lds128(st + 8192  + (wn * 2 + nb) * 512 + lane * 16);
            blv[nb] = lds128(st + 12288 + (wn * 2 + nb) * 512 + lane * 16);
        }
#pragma unroll
        for (int mi = 0; mi < 4; mi++) {
            uint4 ah = lds128(st +        (wm * 4 + mi) * 512 + lane * 16);
            uint4 al = lds128(st + 4096 + (wm * 4 + mi) * 512 + lane * 16);
#pragma unroll
            for (int nb = 0; nb < 2; nb++) {
                uint32_t bh0[2] = {bhv[nb].x, bhv[nb].z};
                uint32_t bl0[2] = {blv[nb].x, blv[nb].z};
                uint32_t bh1[2] = {bhv[nb].y, bhv[nb].w};
                uint32_t bl1[2] = {blv[nb].y, blv[nb].w};
                float* a0 = acc[mi][nb * 2];
                float* a1 = acc[mi][nb * 2 + 1];
                mma_bf16(a0, (const uint32_t*)&ah, bh0);
                mma_bf16(a0, (const uint32_t*)&al, bh0);
                mma_bf16(a0, (const uint32_t*)&ah, bl0);
                mma_bf16(a1, (const uint32_t*)&ah, bh1);
                mma_bf16(a1, (const uint32_t*)&al, bh1);
                mma_bf16(a1, (const uint32_t*)&ah, bl1);
            }
        }
        __syncthreads();
    }

    if (!sym) {
        // row-major f32 epilogue (U)
#pragma unroll
        for (int mi = 0; mi < 4; mi++) {
            const int r = ci0 + wm * 64 + mi * 16 + grp;
#pragma unroll
            for (int nj = 0; nj < 4; nj++) {
                const int c = cj0 + wn * 32 + (nj >> 1) * 16 + (nj & 1) * 8 + 2 * qid;
                *(float2*)&oF[(long long)r * DIMC + c] =
                    make_float2(acc[mi][nj][0], acc[mi][nj][1]);
                *(float2*)&oF[(long long)(r + 8) * DIMC + c] =
                    make_float2(acc[mi][nj][2], acc[mi][nj][3]);
            }
        }
        return;
    }

    // sym epilogue: stage via smem in two 64-row halves, write bf16-packed G
    CP_WAIT(0);
    __syncthreads();
    float* Cst = (float*)smem;   // [64][133]

    for (int h = 0; h < 2; h++) {
        if (wm == h) {
#pragma unroll
            for (int mi = 0; mi < 4; mi++) {
                const int lr = mi * 16 + grp;
#pragma unroll
                for (int nj = 0; nj < 4; nj++) {
                    const int c = wn * 32 + (nj >> 1) * 16 + (nj & 1) * 8 + 2 * qid;
                    Cst[lr * 133 + c]           = acc[mi][nj][0];
                    Cst[lr * 133 + c + 1]       = acc[mi][nj][1];
                    Cst[(lr + 8) * 133 + c]     = acc[mi][nj][2];
                    Cst[(lr + 8) * 133 + c + 1] = acc[mi][nj][3];
                }
            }
        }
        __syncthreads();

        // direct: rows [ci0+h*64, +64) x cols [cj0, +128) -> 1024 uint4
#pragma unroll
        for (int it = 0; it < 4; it++) {
            const int u = it * 256 + tid;
            const int blk = u >> 5, l4 = u & 31;
            const int mbq = blk >> 3, kbq = blk & 7;
            const int rl = mbq * 16 + (l4 >> 2);
            const int kl = kbq * 16 + (l4 & 3) * 2;
            uint4 H, L;
            split2_bf16(Cst[rl * 133 + kl],           Cst[rl * 133 + kl + 1],       H.x, L.x);
            split2_bf16(Cst[(rl + 8) * 133 + kl],     Cst[(rl + 8) * 133 + kl + 1], H.y, L.y);
            split2_bf16(Cst[rl * 133 + kl + 8],       Cst[rl * 133 + kl + 9],       H.z, L.z);
            split2_bf16(Cst[(rl + 8) * 133 + kl + 8], Cst[(rl + 8) * 133 + kl + 9], H.w, L.w);
            const long long gi =
                ((long long)(((ci0 + h * 64) >> 4) + mbq) * 48 + (cj0 >> 4) + kbq) * 32 + l4;
            ((uint4*)oGh)[gi] = H;
            ((uint4*)oGl)[gi] = L;
        }

        if (ti != tj) {
            // mirror: rows [cj0, +128) x k [ci0+h*64, +64) -> 1024 uint4
#pragma unroll
            for (int it = 0; it < 4; it++) {
                const int u = it * 256 + tid;
                const int blk = u >> 5, l4 = u & 31;
                const int mbq = blk >> 2, kbq = blk & 3;
                const int cl = mbq * 16 + (l4 >> 2);       // local col (pack row)
                const int kl = kbq * 16 + (l4 & 3) * 2;    // local row (pack k)
                uint4 H, L;
                split2_bf16(Cst[kl * 133 + cl],           Cst[(kl + 1) * 133 + cl],     H.x, L.x);
                split2_bf16(Cst[kl * 133 + cl + 8],       Cst[(kl + 1) * 133 + cl + 8], H.y, L.y);
                split2_bf16(Cst[(kl + 8) * 133 + cl],     Cst[(kl + 9) * 133 + cl],     H.z, L.z);
                split2_bf16(Cst[(kl + 8) * 133 + cl + 8], Cst[(kl + 9) * 133 + cl + 8], H.w, L.w);
                const long long gi =
                    ((long long)((cj0 >> 4) + mbq) * 48 + (((ci0 + h * 64) >> 4) + kbq)) * 32 + l4;
                ((uint4*)oGh)[gi] = H;
                ((uint4*)oGl)[gi] = L;
            }
        }
        __syncthreads();
    }
}

// ---------------------------------------------------------------------------
// Per (m,b,h): L[d][e] = SCALE * sum_c U[h*64+d][c] * W[c][768+h*64+e]
// then column-wise (over d) softmax -> g_ctx[m][b][h]
// ---------------------------------------------------------------------------
__global__ __launch_bounds__(256) void ctx_kernel(
    const float* __restrict__ Wrgb, const float* __restrict__ Wdepth)
{
    __shared__ float Us[64][68];
    __shared__ float Ws[64][68];

    const int z = blockIdx.y;
    const int m = z >> 4, b = z & 15;
    const int h = blockIdx.x;
    const float* U = &g_U[m][b][0] + (long long)(h * 64) * DIMC;
    const float* W = (m == 0 ? Wrgb : Wdepth) + DIMC + h * 64;

    const int tid = threadIdx.x;
    const int ty = tid >> 4, tx = tid & 15;

    float acc[4][4];
#pragma unroll
    for (int i = 0; i < 4; i++)
#pragma unroll
        for (int j = 0; j < 4; j++) acc[i][j] = 0.f;

    for (int c0 = 0; c0 < DIMC; c0 += 64) {
#pragma unroll
        for (int t = 0; t < 4; t++) {
            const int f4 = tid + t * 256;
            const int r = f4 >> 4;
            const int cg = (f4 & 15) << 2;
            float4 u = *(const float4*)(U + (long long)r * DIMC + c0 + cg);
            Us[r][cg + 0] = u.x; Us[r][cg + 1] = u.y; Us[r][cg + 2] = u.z; Us[r][cg + 3] = u.w;
            float4 w = *(const float4*)(W + (long long)(c0 + r) * (2 * DIMC) + cg);
            Ws[r][cg + 0] = w.x; Ws[r][cg + 1] = w.y; Ws[r][cg + 2] = w.z; Ws[r][cg + 3] = w.w;
        }
        __syncthreads();
#pragma unroll 8
        for (int c = 0; c < 64; c++) {
            float u0 = Us[ty * 4 + 0][c], u1 = Us[ty * 4 + 1][c];
            float u2 = Us[ty * 4 + 2][c], u3 = Us[ty * 4 + 3][c];
            float w0 = Ws[c][tx * 4 + 0], w1 = Ws[c][tx * 4 + 1];
            float w2 = Ws[c][tx * 4 + 2], w3 = Ws[c][tx * 4 + 3];
            acc[0][0] += u0 * w0; acc[0][1] += u0 * w1; acc[0][2] += u0 * w2; acc[0][3] += u0 * w3;
            acc[1][0] += u1 * w0; acc[1][1] += u1 * w1; acc[1][2] += u1 * w2; acc[1][3] += u1 * w3;
            acc[2][0] += u2 * w0; acc[2][1] += u2 * w1; acc[2][2] += u2 * w2; acc[2][3] += u2 * w3;
            acc[3][0] += u3 * w0; acc[3][1] += u3 * w1; acc[3][2] += u3 * w2; acc[3][3] += u3 * w3;
        }
        __syncthreads();
    }

    const float SCALE = 0.125f;
#pragma unroll
    for (int i = 0; i < 4; i++)
#pragma unroll
        for (int j = 0; j < 4; j++)
            Us[ty * 4 + i][tx * 4 + j] = acc[i][j] * SCALE;
    __syncthreads();

    if (tid < 64) {
        const int e = tid;
        float mx = -1e30f;
#pragma unroll 8
        for (int d = 0; d < 64; d++) mx = fmaxf(mx, Us[d][e]);
        float s = 0.f;
#pragma unroll 8
        for (int d = 0; d < 64; d++) {
            float v = expf(Us[d][e] - mx);
            Us[d][e] = v;
            s += v;
        }
        const float inv = 1.f / s;
        float* cx = &g_ctx[m][b][h][0];
#pragma unroll 8
        for (int d = 0; d < 64; d++) cx[d * 64 + e] = Us[d][e] * inv;
    }
}

// ---------------------------------------------------------------------------
// out_m[b, n, h*64+e] = sum_d X_m[b, n, h*64+d] * ctx_{1-m}[b][h][d][e]
// ---------------------------------------------------------------------------
__global__ __launch_bounds__(256) void out_kernel(
    const float* __restrict__ rgb, const float* __restrict__ depth,
    float* __restrict__ out)
{
    __shared__ uint32_t As[64][68];
    __shared__ uint32_t Bs[64][68];

    const int z = blockIdx.z;
    const int m = z >> 4, b = z & 15;
    const int h = blockIdx.y;
    const int n0 = blockIdx.x * 64;

    const float* X = (m == 0 ? rgb : depth) + ((long long)b * NTOK + n0) * DIMC + h * HD;
    const float* cx = &g_ctx[1 - m][b][h][0];
    float* O = out + (long long)m * BATCH * NTOK * DIMC + ((long long)b * NTOK + n0) * DIMC + h * HD;

    const int tid = threadIdx.x;
    const int wid = tid >> 5, lane = tid & 31;
    const int wm = wid >> 2, wn = wid & 3;
    const int grp = lane >> 2, qid = lane & 3;

#pragma unroll
    for (int t = 0; t < 4; t++) {
        const int f4 = tid + t * 256;
        const int r = f4 >> 4;
        const int cg = (f4 & 15) << 2;
        float4 v = *(const float4*)(X + (long long)r * DIMC + cg);
        As[r][cg + 0] = to_tf32(v.x); As[r][cg + 1] = to_tf32(v.y);
        As[r][cg + 2] = to_tf32(v.z); As[r][cg + 3] = to_tf32(v.w);
    }
#pragma unroll
    for (int t = 0; t < 4; t++) {
        const int f4 = tid + t * 256;
        const int d = f4 >> 4;
        const int eg = (f4 & 15) << 2;
        float4 v = *(const float4*)(cx + d * 64 + eg);
        Bs[eg + 0][d] = to_tf32(v.x); Bs[eg + 1][d] = to_tf32(v.y);
        Bs[eg + 2][d] = to_tf32(v.z); Bs[eg + 3][d] = to_tf32(v.w);
    }
    __syncthreads();

    float acc[2][2][4];
#pragma unroll
    for (int a = 0; a < 2; a++)
#pragma unroll
        for (int c = 0; c < 2; c++)
#pragma unroll
            for (int r = 0; r < 4; r++) acc[a][c][r] = 0.f;

#pragma unroll
    for (int ks = 0; ks < 8; ks++) {
        const int kq = (ks << 3) + qid;
        uint32_t ah[2][4], bh[2][2];
#pragma unroll
        for (int mi = 0; mi < 2; mi++) {
            const int i = wm * 32 + mi * 16 + grp;
            ah[mi][0] = As[i][kq];     ah[mi][1] = As[i + 8][kq];
            ah[mi][2] = As[i][kq + 4]; ah[mi][3] = As[i + 8][kq + 4];
        }
#pragma unroll
        for (int nj = 0; nj < 2; nj++) {
            const int n = wn * 16 + nj * 8 + grp;
            bh[nj][0] = Bs[n][kq]; bh[nj][1] = Bs[n][kq + 4];
        }
#pragma unroll
        for (int mi = 0; mi < 2; mi++)
#pragma unroll
            for (int nj = 0; nj < 2; nj++)
                mma_tf32(acc[mi][nj], ah[mi], bh[nj]);
    }

#pragma unroll
    for (int mi = 0; mi < 2; mi++) {
        const int r0 = wm * 32 + mi * 16 + grp;
#pragma unroll
        for (int nj = 0; nj < 2; nj++) {
            const int c0c = wn * 16 + nj * 8 + 2 * qid;
            *(float2*)(O + (long long)r0 * DIMC + c0c) =
                make_float2(acc[mi][nj][0], acc[mi][nj][1]);
            *(float2*)(O + (long long)(r0 + 8) * DIMC + c0c) =
                make_float2(acc[mi][nj][2], acc[mi][nj][3]);
        }
    }
}

// ---------------------------------------------------------------------------
extern "C" void kernel_launch(void* const* d_in, const int* in_sizes, int n_in,
                              void* d_out, int out_size)
{
    const float* rgb = (const float*)d_in[0];
    const float* dep = (const float*)d_in[1];
    const float* Wr  = (const float*)d_in[2];
    const float* Wd  = (const float*)d_in[3];
    float* out = (float*)d_out;

    uint32_t *pXh, *pXl, *pWh, *pWl, *pGh, *pGl;
    float *pU;
    cudaGetSymbolAddress((void**)&pXh, g_Xh);
    cudaGetSymbolAddress((void**)&pXl, g_Xl);
    cudaGetSymbolAddress((void**)&pWh, g_Wh);
    cudaGetSymbolAddress((void**)&pWl, g_Wl);
    cudaGetSymbolAddress((void**)&pGh, g_Gh);
    cudaGetSymbolAddress((void**)&pGl, g_Gl);
    cudaGetSymbolAddress((void**)&pU, g_U);

    cudaFuncSetAttribute(gemm_bf16_kernel,
                         cudaFuncAttributeMaxDynamicSharedMemorySize, GEMM_SMEM);

    const long long XS  = (long long)NTOK * DIMC;          // per-batch X floats
    const long long XPB = (long long)DIMC * (NTOK / 2);    // per-batch packed u32
    const long long GPB = (long long)DIMC * (DIMC / 2);    // per-batch packed G u32
    const long long WPB = (long long)DIMC * (DIMC / 2);
    const long long UB  = (long long)DIMC * DIMC;

    // pre-pass: bf16 split + fragment pack
    pack_bf16_kernel<<<dim3(12, 64, 16), 256>>>(rgb, XS, DIMC, NTOK, pXh, pXl, XPB);
    pack_bf16_kernel<<<dim3(12, 64, 16), 256>>>(dep, XS, DIMC, NTOK,
                                                pXh + 16 * XPB, pXl + 16 * XPB, XPB);
    pack_bf16_kernel<<<dim3(12, 12, 1), 256>>>(Wr, 0, 2 * DIMC, DIMC, pWh, pWl, 0);
    pack_bf16_kernel<<<dim3(12, 12, 1), 256>>>(Wd, 0, 2 * DIMC, DIMC,
                                               pWh + WPB, pWl + WPB, 0);

    // G = XᵀX (symmetric, 21 tiles), epilogue writes packed bf16 G
    gemm_bf16_kernel<<<dim3(21, 16), 256, GEMM_SMEM>>>(
        pXh, pXl, XPB, pXh, pXl, XPB, NTOK, 1, pGh, pGl, nullptr, GPB);
    gemm_bf16_kernel<<<dim3(21, 16), 256, GEMM_SMEM>>>(
        pXh + 16 * XPB, pXl + 16 * XPB, XPB, pXh + 16 * XPB, pXl + 16 * XPB, XPB,
        NTOK, 1, pGh + 16 * GPB, pGl + 16 * GPB, nullptr, GPB);

    // U = Wkᵀ G (G symmetric -> packed G valid as B operand)
    gemm_bf16_kernel<<<dim3(36, 16), 256, GEMM_SMEM>>>(
        pWh, pWl, 0, pGh, pGl, GPB, DIMC, 0, nullptr, nullptr, pU, UB);
    gemm_bf16_kernel<<<dim3(36, 16), 256, GEMM_SMEM>>>(
        pWh + WPB, pWl + WPB, 0, pGh + 16 * GPB, pGl + 16 * GPB, GPB,
        DIMC, 0, nullptr, nullptr, pU + 16 * UB, UB);

    // per-head logits + softmax -> ctx
    ctx_kernel<<<dim3(NHEADS, 32), 256>>>(Wr, Wd);

    // out = X @ blockdiag(ctx_other)
    out_kernel<<<dim3(NTOK / 64, NHEADS, 32), 256>>>(rgb, dep, out);
}

// round 7
// speedup vs baseline: 4.0631x; 1.1190x over previous
#include <cuda_runtime.h>
#include <cuda_bf16.h>
#include <cstdint>

// ---------------------------------------------------------------------------
// KTBCrossAttention restructured (bf16x3 mma.sync, fragment-packed operands):
//   Xh/Xl = pack(split_bf16(Xᵀ))  fragment-ordered (pre-pass, both modalities)
//   G_mb  = XᵀX   (768x768, K=4096, sym)  [3xBF16 m16n8k16, one merged launch]
//   U_mb  = WkᵀG  (768x768, K=768)        [3xBF16, one merged launch]
//   ctx   = softmax_d( s * U[h] @ Wv_h )
//   out   = X @ blockdiag(ctx_other)      [tf32 mma, 128-row tiles]
//
// Pack layout for M[R][K] as bf16 pairs (uint32 = 2 adjacent k):
//   block = (r>>4)*(K>>4) + (k>>4)    (16r x 16k block = 128 uint32)
//   within: lane = (r&7)*4 + ((k>>1)&3), reg = ((r>>3)&1) + 2*((k>>3)&1)
// One LDS.128 per lane = m16n8k16 A-frag. As B operand, the two 8-col halves
// of a 16-row block use regs {x,z} / {y,w} of the same LDS.128.
// ---------------------------------------------------------------------------

#define DIMC 768
#define NTOK 4096
#define BATCH 16
#define NHEADS 12
#define HD 64

#define STAGES 3
#define STAGE_BYTES 32768                    // k32 slab: 4 quarters x 8KB
#define GEMM_SMEM (STAGES * STAGE_BYTES)     // 96 KB
#define OUT_SMEM ((128 * 68 + 64 * 68) * 4)  // 52.2 KB

// scratch (device globals; allocation-free contract)
__device__ uint32_t g_Xh[2][BATCH][DIMC * (NTOK / 2)];   // 201.3 MB
__device__ uint32_t g_Xl[2][BATCH][DIMC * (NTOK / 2)];   // 201.3 MB
__device__ uint32_t g_Wh[2][DIMC * (DIMC / 2)];          // 2.4 MB
__device__ uint32_t g_Wl[2][DIMC * (DIMC / 2)];
__device__ uint32_t g_Gh[2][BATCH][DIMC * (DIMC / 2)];   // 37.7 MB
__device__ uint32_t g_Gl[2][BATCH][DIMC * (DIMC / 2)];   // 37.7 MB
__device__ float    g_U[2][BATCH][DIMC * DIMC];          // 75.5 MB
__device__ float    g_ctx[2][BATCH][NHEADS][HD * HD];    // 6.3 MB

// ---------------------------------------------------------------------------
__device__ __forceinline__ uint32_t smem_to_u32(const void* p) {
    uint32_t a;
    asm("{ .reg .u64 tmp; cvta.to.shared.u64 tmp, %1; cvt.u32.u64 %0, tmp; }"
        : "=r"(a) : "l"(p));
    return a;
}

__device__ __forceinline__ void cp16(uint32_t saddr, const void* g) {
    asm volatile("cp.async.cg.shared.global [%0], [%1], 16;" :: "r"(saddr), "l"(g));
}
#define CP_COMMIT() asm volatile("cp.async.commit_group;" ::: "memory")
#define CP_WAIT(n)  asm volatile("cp.async.wait_group %0;" :: "n"(n) : "memory")

__device__ __forceinline__ uint4 lds128(uint32_t a) {
    uint4 v;
    asm volatile("ld.shared.v4.b32 {%0,%1,%2,%3}, [%4];"
                 : "=r"(v.x), "=r"(v.y), "=r"(v.z), "=r"(v.w) : "r"(a));
    return v;
}

__device__ __forceinline__ void mma_bf16(float* d, const uint32_t* a, const uint32_t* b) {
    asm volatile(
        "mma.sync.aligned.m16n8k16.row.col.f32.bf16.bf16.f32 "
        "{%0,%1,%2,%3}, {%4,%5,%6,%7}, {%8,%9}, {%0,%1,%2,%3};"
        : "+f"(d[0]), "+f"(d[1]), "+f"(d[2]), "+f"(d[3])
        : "r"(a[0]), "r"(a[1]), "r"(a[2]), "r"(a[3]), "r"(b[0]), "r"(b[1]));
}

__device__ __forceinline__ void mma_tf32(float* d, const uint32_t* a, const uint32_t* b) {
    asm volatile(
        "mma.sync.aligned.m16n8k8.row.col.f32.tf32.tf32.f32 "
        "{%0,%1,%2,%3}, {%4,%5,%6,%7}, {%8,%9}, {%0,%1,%2,%3};"
        : "+f"(d[0]), "+f"(d[1]), "+f"(d[2]), "+f"(d[3])
        : "r"(a[0]), "r"(a[1]), "r"(a[2]), "r"(a[3]), "r"(b[0]), "r"(b[1]));
}

__device__ __forceinline__ uint32_t to_tf32(float v) {
    uint32_t t;
    asm("cvt.rna.tf32.f32 %0, %1;" : "=r"(t) : "f"(v));
    return t;
}

// split two floats into packed bf16x2 hi / lo
__device__ __forceinline__ void split2_bf16(float a, float b,
                                            uint32_t& h, uint32_t& l) {
    __nv_bfloat16 ha = __float2bfloat16_rn(a);
    __nv_bfloat16 hb = __float2bfloat16_rn(b);
    float ra = a - __bfloat162float(ha);
    float rb = b - __bfloat162float(hb);
    __nv_bfloat16 la = __float2bfloat16_rn(ra);
    __nv_bfloat16 lb = __float2bfloat16_rn(rb);
    __nv_bfloat162 hp; hp.x = ha; hp.y = hb;
    __nv_bfloat162 lp; lp.x = la; lp.y = lb;
    h = *reinterpret_cast<uint32_t*>(&hp);
    l = *reinterpret_cast<uint32_t*>(&lp);
}

// ---------------------------------------------------------------------------
// Pre-pass: read src[k][r] (row stride srcLd), transpose via smem, bf16-split,
// write fragment-packed hi/lo arrays. Tile = 64r x 64k.
// z: m = z / zdiv picks srcA/srcB, b = z % zdiv.
// ---------------------------------------------------------------------------
__global__ __launch_bounds__(256) void pack_bf16_kernel(
    const float* __restrict__ srcA, const float* __restrict__ srcB,
    long long srcBStr, int srcLd, int K, int zdiv,
    uint32_t* __restrict__ oH, uint32_t* __restrict__ oL, long long dstBStr)
{
    __shared__ float t[64][65];
    const int z = blockIdx.z;
    const int m = z / zdiv, b = z % zdiv;
    const float* src = (m == 0 ? srcA : srcB) + (long long)b * srcBStr;
    oH += (long long)z * dstBStr;
    oL += (long long)z * dstBStr;

    const int r0 = blockIdx.x * 64, k0 = blockIdx.y * 64;
    const int tid = threadIdx.x;
    const int Kb16 = K >> 4;

#pragma unroll
    for (int it = 0; it < 16; it++) {
        const int row = it * 4 + (tid >> 6);   // k-local
        const int col = tid & 63;              // r-local
        t[row][col] = src[(long long)(k0 + row) * srcLd + r0 + col];
    }
    __syncthreads();

#pragma unroll
    for (int it = 0; it < 8; it++) {
        const int e = it * 256 + tid;     // 2048 uint32 per tile
        const int w = e & 127;
        const int blk = e >> 7;           // 16 blocks (4 rb x 4 kb)
        const int mb = blk >> 2, kb = blk & 3;
        const int lane = w >> 2, reg = w & 3;
        const int rr = mb * 16 + (lane >> 2) + 8 * (reg & 1);
        const int kk = kb * 16 + ((lane & 3) + 4 * ((reg >> 1) & 1)) * 2;
        uint32_t h, l;
        split2_bf16(t[kk][rr], t[kk + 1][rr], h, l);
        const long long gidx =
            (long long)(((r0 >> 4) + mb) * Kb16 + (k0 >> 4) + kb) * 128 + w;
        oH[gidx] = h;
        oL[gidx] = l;
    }
}

// ---------------------------------------------------------------------------
// GEMM C[i][j] = sum_k A[i][k] B[j][k], operands fragment-packed bf16 hi/lo.
// 128x128 CTA tile, k32 slab, 3-stage cp.async pipeline, 3xBF16 mma.sync.
// z = blockIdx.y in [0,32): A += (z/aDiv)*aBStr, B += z*bBStr, out += z*oBStr.
// sym=1: triangular tiles of G; epilogue stages via smem, writes bf16 pack.
// sym=0: full 6x6 tiles; epilogue writes row-major f32 (U).
// ---------------------------------------------------------------------------
__global__ __launch_bounds__(256, 2) void gemm_bf16_kernel(
    const uint32_t* __restrict__ Ah, const uint32_t* __restrict__ Al,
    long long aBStr, int aDiv,
    const uint32_t* __restrict__ Bh, const uint32_t* __restrict__ Bl,
    long long bBStr,
    int K, int sym,
    uint32_t* __restrict__ oGh, uint32_t* __restrict__ oGl,
    float* __restrict__ oF, long long oBStr)
{
    extern __shared__ char smem[];
    const uint32_t smem_base = smem_to_u32(smem);
    const int tid = threadIdx.x;
    const int wid = tid >> 5, lane = tid & 31;
    const int wm = wid >> 2, wn = wid & 3;
    const int grp = lane >> 2, qid = lane & 3;
    const int z = blockIdx.y;

    const long long aOff = (long long)(z / aDiv) * aBStr;
    Ah += aOff; Al += aOff;
    Bh += z * bBStr; Bl += z * bBStr;
    if (oGh) { oGh += z * oBStr; oGl += z * oBStr; }
    if (oF)  { oF  += z * oBStr; }

    int ti, tj;
    if (sym) {
        int rem = blockIdx.x;
        ti = 0;
        while (rem >= 6 - ti) { rem -= (6 - ti); ti++; }
        tj = ti + rem;
    } else {
        ti = blockIdx.x / 6;
        tj = blockIdx.x % 6;
    }
    const int ci0 = ti * 128, cj0 = tj * 128;
    const int Kb16 = K >> 4;
    const int NS = K >> 5;              // k32 slabs

    // copy roles: quarter q in {Ah, Al, Bh, Bl}, 64 threads each.
    // Per slab each quarter moves 8KB: 8 rowblocks x 2 kblocks x 128 u32.
    const int q = tid >> 6, t6 = tid & 63;
    const int mb = t6 >> 3, i8 = t6 & 7;
    const uint32_t* gq = (q == 0) ? Ah : (q == 1) ? Al : (q == 2) ? Bh : Bl;
    const int rowblk0 = ((q < 2) ? ci0 : cj0) >> 4;
    const uint32_t* gsrc = gq + (long long)(rowblk0 + mb) * Kb16 * 128 + i8 * 16;
    const uint32_t sdst0 = smem_base + q * 8192 + mb * 1024 + i8 * 64;

    float acc[4][4][4];
#pragma unroll
    for (int a = 0; a < 4; a++)
#pragma unroll
        for (int b = 0; b < 4; b++)
#pragma unroll
            for (int c = 0; c < 4; c++) acc[a][b][c] = 0.f;

    // prologue: stages 0,1 (slabs 0,1)
#pragma unroll
    for (int s = 0; s < STAGES - 1; s++) {
        const uint32_t* g = gsrc + (long long)(2 * s) * 128;
        const uint32_t d = sdst0 + s * STAGE_BYTES;
#pragma unroll
        for (int kb = 0; kb < 2; kb++)
#pragma unroll
            for (int i = 0; i < 4; i++)
                cp16(d + kb * 512 + i * 16, g + kb * 128 + i * 4);
        CP_COMMIT();
    }

    int sidx = 0, pidx = STAGES - 1;
    for (int s = 0; s < NS; s++) {
        if (s + STAGES - 1 < NS) {
            const uint32_t* g = gsrc + (long long)(2 * (s + STAGES - 1)) * 128;
            const uint32_t d = sdst0 + pidx * STAGE_BYTES;
#pragma unroll
            for (int kb = 0; kb < 2; kb++)
#pragma unroll
                for (int i = 0; i < 4; i++)
                    cp16(d + kb * 512 + i * 16, g + kb * 128 + i * 4);
        }
        CP_COMMIT();
        CP_WAIT(STAGES - 1);
        __syncthreads();

        const uint32_t st = smem_base + sidx * STAGE_BYTES;
#pragma unroll
        for (int kb = 0; kb < 2; kb++) {
            uint4 bhv[2], blv[2];
#pragma unroll
            for (int nb = 0; nb < 2; nb++) {
                const uint32_t ba = st + (wn * 2 + nb) * 1024 + kb * 512 + lane * 16;
                bhv[nb] = lds128(ba + 16384);
                blv[nb] = lds128(ba + 24576);
            }
#pragma unroll
            for (int mi = 0; mi < 4; mi++) {
                const uint32_t aa = st + (wm * 4 + mi) * 1024 + kb * 512 + lane * 16;
                uint4 ah = lds128(aa);
                uint4 al = lds128(aa + 8192);
#pragma unroll
                for (int nb = 0; nb < 2; nb++) {
                    uint32_t bh0[2] = {bhv[nb].x, bhv[nb].z};
                    uint32_t bl0[2] = {blv[nb].x, blv[nb].z};
                    uint32_t bh1[2] = {bhv[nb].y, bhv[nb].w};
                    uint32_t bl1[2] = {blv[nb].y, blv[nb].w};
                    float* a0 = acc[mi][nb * 2];
                    float* a1 = acc[mi][nb * 2 + 1];
                    mma_bf16(a0, (const uint32_t*)&ah, bh0);
                    mma_bf16(a0, (const uint32_t*)&al, bh0);
                    mma_bf16(a0, (const uint32_t*)&ah, bl0);
                    mma_bf16(a1, (const uint32_t*)&ah, bh1);
                    mma_bf16(a1, (const uint32_t*)&al, bh1);
                    mma_bf16(a1, (const uint32_t*)&ah, bl1);
                }
            }
        }
        __syncthreads();
        if (++sidx == STAGES) sidx = 0;
        if (++pidx == STAGES) pidx = 0;
    }

    if (!sym) {
        // row-major f32 epilogue (U)
#pragma unroll
        for (int mi = 0; mi < 4; mi++) {
            const int r = ci0 + wm * 64 + mi * 16 + grp;
#pragma unroll
            for (int nj = 0; nj < 4; nj++) {
                const int c = cj0 + wn * 32 + (nj >> 1) * 16 + (nj & 1) * 8 + 2 * qid;
                *(float2*)&oF[(long long)r * DIMC + c] =
                    make_float2(acc[mi][nj][0], acc[mi][nj][1]);
                *(float2*)&oF[(long long)(r + 8) * DIMC + c] =
                    make_float2(acc[mi][nj][2], acc[mi][nj][3]);
            }
        }
        return;
    }

    // sym epilogue: stage via smem in two 64-row halves, write bf16-packed G
    CP_WAIT(0);
    __syncthreads();
    float* Cst = (float*)smem;   // [64][133]

    for (int h = 0; h < 2; h++) {
        if (wm == h) {
#pragma unroll
            for (int mi = 0; mi < 4; mi++) {
                const int lr = mi * 16 + grp;
#pragma unroll
                for (int nj = 0; nj < 4; nj++) {
                    const int c = wn * 32 + (nj >> 1) * 16 + (nj & 1) * 8 + 2 * qid;
                    Cst[lr * 133 + c]           = acc[mi][nj][0];
                    Cst[lr * 133 + c + 1]       = acc[mi][nj][1];
                    Cst[(lr + 8) * 133 + c]     = acc[mi][nj][2];
                    Cst[(lr + 8) * 133 + c + 1] = acc[mi][nj][3];
                }
            }
        }
        __syncthreads();

        // direct: rows [ci0+h*64, +64) x cols [cj0, +128) -> 1024 uint4
#pragma unroll
        for (int it = 0; it < 4; it++) {
            const int u = it * 256 + tid;
            const int blk = u >> 5, l4 = u & 31;
            const int mbq = blk >> 3, kbq = blk & 7;
            const int rl = mbq * 16 + (l4 >> 2);
            const int kl = kbq * 16 + (l4 & 3) * 2;
            uint4 H, L;
            split2_bf16(Cst[rl * 133 + kl],           Cst[rl * 133 + kl + 1],       H.x, L.x);
            split2_bf16(Cst[(rl + 8) * 133 + kl],     Cst[(rl + 8) * 133 + kl + 1], H.y, L.y);
            split2_bf16(Cst[rl * 133 + kl + 8],       Cst[rl * 133 + kl + 9],       H.z, L.z);
            split2_bf16(Cst[(rl + 8) * 133 + kl + 8], Cst[(rl + 8) * 133 + kl + 9], H.w, L.w);
            const long long gi =
                ((long long)(((ci0 + h * 64) >> 4) + mbq) * 48 + (cj0 >> 4) + kbq) * 32 + l4;
            ((uint4*)oGh)[gi] = H;
            ((uint4*)oGl)[gi] = L;
        }

        if (ti != tj) {
            // mirror: rows [cj0, +128) x k [ci0+h*64, +64) -> 1024 uint4
#pragma unroll
            for (int it = 0; it < 4; it++) {
                const int u = it * 256 + tid;
                const int blk = u >> 5, l4 = u & 31;
                const int mbq = blk >> 2, kbq = blk & 3;
                const int cl = mbq * 16 + (l4 >> 2);       // local col (pack row)
                const int kl = kbq * 16 + (l4 & 3) * 2;    // local row (pack k)
                uint4 H, L;
                split2_bf16(Cst[kl * 133 + cl],           Cst[(kl + 1) * 133 + cl],     H.x, L.x);
                split2_bf16(Cst[kl * 133 + cl + 8],       Cst[(kl + 1) * 133 + cl + 8], H.y, L.y);
                split2_bf16(Cst[(kl + 8) * 133 + cl],     Cst[(kl + 9) * 133 + cl],     H.z, L.z);
                split2_bf16(Cst[(kl + 8) * 133 + cl + 8], Cst[(kl + 9) * 133 + cl + 8], H.w, L.w);
                const long long gi =
                    ((long long)((cj0 >> 4) + mbq) * 48 + (((ci0 + h * 64) >> 4) + kbq)) * 32 + l4;
                ((uint4*)oGh)[gi] = H;
                ((uint4*)oGl)[gi] = L;
            }
        }
        __syncthreads();
    }
}

// ---------------------------------------------------------------------------
// Per (m,b,h): L[d][e] = SCALE * sum_c U[h*64+d][c] * W[c][768+h*64+e]
// then column-wise (over d) softmax -> g_ctx[m][b][h]
// ---------------------------------------------------------------------------
__global__ __launch_bounds__(256) void ctx_kernel(
    const float* __restrict__ Wrgb, const float* __restrict__ Wdepth)
{
    __shared__ float Us[64][68];
    __shared__ float Ws[64][68];

    const int z = blockIdx.y;
    const int m = z >> 4, b = z & 15;
    const int h = blockIdx.x;
    const float* U = &g_U[m][b][0] + (long long)(h * 64) * DIMC;
    const float* W = (m == 0 ? Wrgb : Wdepth) + DIMC + h * 64;

    const int tid = threadIdx.x;
    const int ty = tid >> 4, tx = tid & 15;

    float acc[4][4];
#pragma unroll
    for (int i = 0; i < 4; i++)
#pragma unroll
        for (int j = 0; j < 4; j++) acc[i][j] = 0.f;

    for (int c0 = 0; c0 < DIMC; c0 += 64) {
#pragma unroll
        for (int t = 0; t < 4; t++) {
            const int f4 = tid + t * 256;
            const int r = f4 >> 4;
            const int cg = (f4 & 15) << 2;
            float4 u = *(const float4*)(U + (long long)r * DIMC + c0 + cg);
            Us[r][cg + 0] = u.x; Us[r][cg + 1] = u.y; Us[r][cg + 2] = u.z; Us[r][cg + 3] = u.w;
            float4 w = *(const float4*)(W + (long long)(c0 + r) * (2 * DIMC) + cg);
            Ws[r][cg + 0] = w.x; Ws[r][cg + 1] = w.y; Ws[r][cg + 2] = w.z; Ws[r][cg + 3] = w.w;
        }
        __syncthreads();
#pragma unroll 8
        for (int c = 0; c < 64; c++) {
            float u0 = Us[ty * 4 + 0][c], u1 = Us[ty * 4 + 1][c];
            float u2 = Us[ty * 4 + 2][c], u3 = Us[ty * 4 + 3][c];
            float w0 = Ws[c][tx * 4 + 0], w1 = Ws[c][tx * 4 + 1];
            float w2 = Ws[c][tx * 4 + 2], w3 = Ws[c][tx * 4 + 3];
            acc[0][0] += u0 * w0; acc[0][1] += u0 * w1; acc[0][2] += u0 * w2; acc[0][3] += u0 * w3;
            acc[1][0] += u1 * w0; acc[1][1] += u1 * w1; acc[1][2] += u1 * w2; acc[1][3] += u1 * w3;
            acc[2][0] += u2 * w0; acc[2][1] += u2 * w1; acc[2][2] += u2 * w2; acc[2][3] += u2 * w3;
            acc[3][0] += u3 * w0; acc[3][1] += u3 * w1; acc[3][2] += u3 * w2; acc[3][3] += u3 * w3;
        }
        __syncthreads();
    }

    const float SCALE = 0.125f;
#pragma unroll
    for (int i = 0; i < 4; i++)
#pragma unroll
        for (int j = 0; j < 4; j++)
            Us[ty * 4 + i][tx * 4 + j] = acc[i][j] * SCALE;
    __syncthreads();

    if (tid < 64) {
        const int e = tid;
        float mx = -1e30f;
#pragma unroll 8
        for (int d = 0; d < 64; d++) mx = fmaxf(mx, Us[d][e]);
        float s = 0.f;
#pragma unroll 8
        for (int d = 0; d < 64; d++) {
            float v = expf(Us[d][e] - mx);
            Us[d][e] = v;
            s += v;
        }
        const float inv = 1.f / s;
        float* cx = &g_ctx[m][b][h][0];
#pragma unroll 8
        for (int d = 0; d < 64; d++) cx[d * 64 + e] = Us[d][e] * inv;
    }
}

// ---------------------------------------------------------------------------
// out_m[b, n, h*64+e] = sum_d X_m[b, n, h*64+d] * ctx_{1-m}[b][h][d][e]
// 128-row tiles, tf32 mma, K=64. Dynamic smem: As[128][68] u32, Bs[64][68].
// ---------------------------------------------------------------------------
__global__ __launch_bounds__(256) void out_kernel(
    const float* __restrict__ rgb, const float* __restrict__ depth,
    float* __restrict__ out)
{
    extern __shared__ char smem[];
    uint32_t* As = (uint32_t*)smem;                 // [128][68]
    uint32_t* Bs = (uint32_t*)smem + 128 * 68;      // [64][68]

    const int z = blockIdx.z;
    const int m = z >> 4, b = z & 15;
    const int h = blockIdx.y;
    const int n0 = blockIdx.x * 128;

    const float* X = (m == 0 ? rgb : depth) + ((long long)b * NTOK + n0) * DIMC + h * HD;
    const float* cx = &g_ctx[1 - m][b][h][0];
    float* O = out + (long long)m * BATCH * NTOK * DIMC + ((long long)b * NTOK + n0) * DIMC + h * HD;

    const int tid = threadIdx.x;
    const int wid = tid >> 5, lane = tid & 31;
    const int wm = wid >> 2, wn = wid & 3;
    const int grp = lane >> 2, qid = lane & 3;

#pragma unroll
    for (int t = 0; t < 8; t++) {
        const int f4 = tid + t * 256;
        const int r = f4 >> 4;
        const int cg = (f4 & 15) << 2;
        float4 v = *(const float4*)(X + (long long)r * DIMC + cg);
        As[r * 68 + cg + 0] = to_tf32(v.x); As[r * 68 + cg + 1] = to_tf32(v.y);
        As[r * 68 + cg + 2] = to_tf32(v.z); As[r * 68 + cg + 3] = to_tf32(v.w);
    }
#pragma unroll
    for (int t = 0; t < 4; t++) {
        const int f4 = tid + t * 256;
        const int d = f4 >> 4;
        const int eg = (f4 & 15) << 2;
        float4 v = *(const float4*)(cx + d * 64 + eg);
        Bs[(eg + 0) * 68 + d] = to_tf32(v.x); Bs[(eg + 1) * 68 + d] = to_tf32(v.y);
        Bs[(eg + 2) * 68 + d] = to_tf32(v.z); Bs[(eg + 3) * 68 + d] = to_tf32(v.w);
    }
    __syncthreads();

    float acc[4][2][4];
#pragma unroll
    for (int a = 0; a < 4; a++)
#pragma unroll
        for (int c = 0; c < 2; c++)
#pragma unroll
            for (int r = 0; r < 4; r++) acc[a][c][r] = 0.f;

#pragma unroll
    for (int ks = 0; ks < 8; ks++) {
        const int kq = (ks << 3) + qid;
        uint32_t ah[4][4], bh[2][2];
#pragma unroll
        for (int mi = 0; mi < 4; mi++) {
            const int i = wm * 64 + mi * 16 + grp;
            ah[mi][0] = As[i * 68 + kq];           ah[mi][1] = As[(i + 8) * 68 + kq];
            ah[mi][2] = As[i * 68 + kq + 4];       ah[mi][3] = As[(i + 8) * 68 + kq + 4];
        }
#pragma unroll
        for (int nj = 0; nj < 2; nj++) {
            const int n = wn * 16 + nj * 8 + grp;
            bh[nj][0] = Bs[n * 68 + kq]; bh[nj][1] = Bs[n * 68 + kq + 4];
        }
#pragma unroll
        for (int mi = 0; mi < 4; mi++)
#pragma unroll
            for (int nj = 0; nj < 2; nj++)
                mma_tf32(acc[mi][nj], ah[mi], bh[nj]);
    }

#pragma unroll
    for (int mi = 0; mi < 4; mi++) {
        const int r0 = wm * 64 + mi * 16 + grp;
#pragma unroll
        for (int nj = 0; nj < 2; nj++) {
            const int c0c = wn * 16 + nj * 8 + 2 * qid;
            *(float2*)(O + (long long)r0 * DIMC + c0c) =
                make_float2(acc[mi][nj][0], acc[mi][nj][1]);
            *(float2*)(O + (long long)(r0 + 8) * DIMC + c0c) =
                make_float2(acc[mi][nj][2], acc[mi][nj][3]);
        }
    }
}

// ---------------------------------------------------------------------------
extern "C" void kernel_launch(void* const* d_in, const int* in_sizes, int n_in,
                              void* d_out, int out_size)
{
    const float* rgb = (const float*)d_in[0];
    const float* dep = (const float*)d_in[1];
    const float* Wr  = (const float*)d_in[2];
    const float* Wd  = (const float*)d_in[3];
    float* out = (float*)d_out;

    uint32_t *pXh, *pXl, *pWh, *pWl, *pGh, *pGl;
    float *pU;
    cudaGetSymbolAddress((void**)&pXh, g_Xh);
    cudaGetSymbolAddress((void**)&pXl, g_Xl);
    cudaGetSymbolAddress((void**)&pWh, g_Wh);
    cudaGetSymbolAddress((void**)&pWl, g_Wl);
    cudaGetSymbolAddress((void**)&pGh, g_Gh);
    cudaGetSymbolAddress((void**)&pGl, g_Gl);
    cudaGetSymbolAddress((void**)&pU, g_U);

    cudaFuncSetAttribute(gemm_bf16_kernel,
                         cudaFuncAttributeMaxDynamicSharedMemorySize, GEMM_SMEM);
    cudaFuncSetAttribute(out_kernel,
                         cudaFuncAttributeMaxDynamicSharedMemorySize, OUT_SMEM);

    const long long XS  = (long long)NTOK * DIMC;          // per-batch X floats
    const long long XPB = (long long)DIMC * (NTOK / 2);    // per-batch packed u32
    const long long GPB = (long long)DIMC * (DIMC / 2);    // per-batch packed G u32
    const long long WPB = (long long)DIMC * (DIMC / 2);
    const long long UB  = (long long)DIMC * DIMC;

    // pre-pass: bf16 split + fragment pack (merged: z covers both modalities)
    pack_bf16_kernel<<<dim3(12, 64, 32), 256>>>(rgb, dep, XS, DIMC, NTOK, 16,
                                                pXh, pXl, XPB);
    pack_bf16_kernel<<<dim3(12, 12, 2), 256>>>(Wr, Wd, 0, 2 * DIMC, DIMC, 1,
                                               pWh, pWl, WPB);

    // G = XᵀX (symmetric, 21 tiles x 32 batch-modality), packed bf16 G out
    gemm_bf16_kernel<<<dim3(21, 32), 256, GEMM_SMEM>>>(
        pXh, pXl, XPB, 1, pXh, pXl, XPB, NTOK, 1, pGh, pGl, nullptr, GPB);

    // U = Wkᵀ G (36 tiles x 32), f32 U out
    gemm_bf16_kernel<<<dim3(36, 32), 256, GEMM_SMEM>>>(
        pWh, pWl, WPB, 16, pGh, pGl, GPB, DIMC, 0, nullptr, nullptr, pU, UB);

    // per-head logits + softmax -> ctx
    ctx_kernel<<<dim3(NHEADS, 32), 256>>>(Wr, Wd);

    // out = X @ blockdiag(ctx_other), 128-row tiles
    out_kernel<<<dim3(NTOK / 128, NHEADS, 32), 256, OUT_SMEM>>>(rgb, dep, out);
}

// round 8
// speedup vs baseline: 4.8147x; 1.1850x over previous
#include <cuda_runtime.h>
#include <cuda_bf16.h>
#include <cstdint>

// ---------------------------------------------------------------------------
// KTBCrossAttention restructured (bf16x3 mma.sync, fragment-packed operands):
//   Xh/Xl = pack(split_bf16(Xᵀ))  fragment-ordered (pre-pass, both modalities)
//   G_mb  = XᵀX   (768x768, K=4096, sym)  [3xBF16 m16n8k16, 64x64 warp tiles]
//   U_mb  = WkᵀG  (768x768, K=768)        [3xBF16]
//   ctx   = softmax_d( s * U[h] @ Wv_h )
//   out   = X @ blockdiag(ctx_other)      [tf32 mma, 128-row tiles]
//
// Pack layout for M[R][K] as bf16 pairs (uint32 = 2 adjacent k):
//   block = (r>>4)*(K>>4) + (k>>4)    (16r x 16k block = 128 uint32)
//   within: lane = (r&7)*4 + ((k>>1)&3), reg = ((r>>3)&1) + 2*((k>>3)&1)
// One LDS.128 per lane = m16n8k16 A-frag. As B operand, the two 8-col halves
// of a 16-row block use regs {x,z} / {y,w} of the same LDS.128.
// ---------------------------------------------------------------------------

#define DIMC 768
#define NTOK 4096
#define BATCH 16
#define NHEADS 12
#define HD 64

#define STAGES 3
#define STAGE_BYTES 32768                    // k32 slab: 4 quarters x 8KB
#define GEMM_SMEM (STAGES * STAGE_BYTES)     // 96 KB
#define OUT_SMEM ((128 * 68 + 64 * 68) * 4)  // 52.2 KB

// scratch (device globals; allocation-free contract)
__device__ uint32_t g_Xh[2][BATCH][DIMC * (NTOK / 2)];   // 201.3 MB
__device__ uint32_t g_Xl[2][BATCH][DIMC * (NTOK / 2)];   // 201.3 MB
__device__ uint32_t g_Wh[2][DIMC * (DIMC / 2)];          // 2.4 MB
__device__ uint32_t g_Wl[2][DIMC * (DIMC / 2)];
__device__ uint32_t g_Gh[2][BATCH][DIMC * (DIMC / 2)];   // 37.7 MB
__device__ uint32_t g_Gl[2][BATCH][DIMC * (DIMC / 2)];   // 37.7 MB
__device__ float    g_U[2][BATCH][DIMC * DIMC];          // 75.5 MB
__device__ float    g_ctx[2][BATCH][NHEADS][HD * HD];    // 6.3 MB

// ---------------------------------------------------------------------------
__device__ __forceinline__ uint32_t smem_to_u32(const void* p) {
    uint32_t a;
    asm("{ .reg .u64 tmp; cvta.to.shared.u64 tmp, %1; cvt.u32.u64 %0, tmp; }"
        : "=r"(a) : "l"(p));
    return a;
}

__device__ __forceinline__ void cp16(uint32_t saddr, const void* g) {
    asm volatile("cp.async.cg.shared.global [%0], [%1], 16;" :: "r"(saddr), "l"(g));
}
#define CP_COMMIT() asm volatile("cp.async.commit_group;" ::: "memory")
#define CP_WAIT(n)  asm volatile("cp.async.wait_group %0;" :: "n"(n) : "memory")

__device__ __forceinline__ uint4 lds128(uint32_t a) {
    uint4 v;
    asm volatile("ld.shared.v4.b32 {%0,%1,%2,%3}, [%4];"
                 : "=r"(v.x), "=r"(v.y), "=r"(v.z), "=r"(v.w) : "r"(a));
    return v;
}

__device__ __forceinline__ void mma_bf16(float* d, const uint32_t* a, const uint32_t* b) {
    asm volatile(
        "mma.sync.aligned.m16n8k16.row.col.f32.bf16.bf16.f32 "
        "{%0,%1,%2,%3}, {%4,%5,%6,%7}, {%8,%9}, {%0,%1,%2,%3};"
        : "+f"(d[0]), "+f"(d[1]), "+f"(d[2]), "+f"(d[3])
        : "r"(a[0]), "r"(a[1]), "r"(a[2]), "r"(a[3]), "r"(b[0]), "r"(b[1]));
}

__device__ __forceinline__ void mma_tf32(float* d, const uint32_t* a, const uint32_t* b) {
    asm volatile(
        "mma.sync.aligned.m16n8k8.row.col.f32.tf32.tf32.f32 "
        "{%0,%1,%2,%3}, {%4,%5,%6,%7}, {%8,%9}, {%0,%1,%2,%3};"
        : "+f"(d[0]), "+f"(d[1]), "+f"(d[2]), "+f"(d[3])
        : "r"(a[0]), "r"(a[1]), "r"(a[2]), "r"(a[3]), "r"(b[0]), "r"(b[1]));
}

__device__ __forceinline__ uint32_t to_tf32(float v) {
    uint32_t t;
    asm("cvt.rna.tf32.f32 %0, %1;" : "=r"(t) : "f"(v));
    return t;
}

// split two floats into packed bf16x2 hi / lo
__device__ __forceinline__ void split2_bf16(float a, float b,
                                            uint32_t& h, uint32_t& l) {
    __nv_bfloat16 ha = __float2bfloat16_rn(a);
    __nv_bfloat16 hb = __float2bfloat16_rn(b);
    float ra = a - __bfloat162float(ha);
    float rb = b - __bfloat162float(hb);
    __nv_bfloat16 la = __float2bfloat16_rn(ra);
    __nv_bfloat16 lb = __float2bfloat16_rn(rb);
    __nv_bfloat162 hp; hp.x = ha; hp.y = hb;
    __nv_bfloat162 lp; lp.x = la; lp.y = lb;
    h = *reinterpret_cast<uint32_t*>(&hp);
    l = *reinterpret_cast<uint32_t*>(&lp);
}

// ---------------------------------------------------------------------------
// Pre-pass: read src[k][r] (row stride srcLd), transpose via smem, bf16-split,
// write fragment-packed hi/lo arrays. Tile = 64r x 64k.
// z: m = z / zdiv picks srcA/srcB, b = z % zdiv.
// ---------------------------------------------------------------------------
__global__ __launch_bounds__(256) void pack_bf16_kernel(
    const float* __restrict__ srcA, const float* __restrict__ srcB,
    long long srcBStr, int srcLd, int K, int zdiv,
    uint32_t* __restrict__ oH, uint32_t* __restrict__ oL, long long dstBStr)
{
    __shared__ float t[64][65];
    const int z = blockIdx.z;
    const int m = z / zdiv, b = z % zdiv;
    const float* src = (m == 0 ? srcA : srcB) + (long long)b * srcBStr;
    oH += (long long)z * dstBStr;
    oL += (long long)z * dstBStr;

    const int r0 = blockIdx.x * 64, k0 = blockIdx.y * 64;
    const int tid = threadIdx.x;
    const int Kb16 = K >> 4;

#pragma unroll
    for (int it = 0; it < 16; it++) {
        const int row = it * 4 + (tid >> 6);   // k-local
        const int col = tid & 63;              // r-local
        t[row][col] = src[(long long)(k0 + row) * srcLd + r0 + col];
    }
    __syncthreads();

#pragma unroll
    for (int it = 0; it < 8; it++) {
        const int e = it * 256 + tid;     // 2048 uint32 per tile
        const int w = e & 127;
        const int blk = e >> 7;           // 16 blocks (4 rb x 4 kb)
        const int mb = blk >> 2, kb = blk & 3;
        const int lane = w >> 2, reg = w & 3;
        const int rr = mb * 16 + (lane >> 2) + 8 * (reg & 1);
        const int kk = kb * 16 + ((lane & 3) + 4 * ((reg >> 1) & 1)) * 2;
        uint32_t h, l;
        split2_bf16(t[kk][rr], t[kk + 1][rr], h, l);
        const long long gidx =
            (long long)(((r0 >> 4) + mb) * Kb16 + (k0 >> 4) + kb) * 128 + w;
        oH[gidx] = h;
        oL[gidx] = l;
    }
}

// ---------------------------------------------------------------------------
// GEMM C[i][j] = sum_k A[i][k] B[j][k], operands fragment-packed bf16 hi/lo.
// 128x128 CTA tile, FOUR warps of 64x64, k32 slab, 3-stage cp.async pipeline,
// 3xBF16 mma.sync. 96 MMA per warp per k16 against 16 LDS.128 (6:1).
// z = blockIdx.y in [0,32): A += (z/aDiv)*aBStr, B += z*bBStr, out += z*oBStr.
// sym=1: triangular tiles of G; epilogue stages via smem, writes bf16 pack.
// sym=0: full 6x6 tiles; epilogue writes row-major f32 (U).
// ---------------------------------------------------------------------------
__global__ __launch_bounds__(128, 2) void gemm_bf16_kernel(
    const uint32_t* __restrict__ Ah, const uint32_t* __restrict__ Al,
    long long aBStr, int aDiv,
    const uint32_t* __restrict__ Bh, const uint32_t* __restrict__ Bl,
    long long bBStr,
    int K, int sym,
    uint32_t* __restrict__ oGh, uint32_t* __restrict__ oGl,
    float* __restrict__ oF, long long oBStr)
{
    extern __shared__ char smem[];
    const uint32_t smem_base = smem_to_u32(smem);
    const int tid = threadIdx.x;
    const int wid = tid >> 5, lane = tid & 31;
    const int wm = wid >> 1, wnn = wid & 1;      // 2x2 warps of 64x64
    const int grp = lane >> 2, qid = lane & 3;
    const int z = blockIdx.y;

    const long long aOff = (long long)(z / aDiv) * aBStr;
    Ah += aOff; Al += aOff;
    Bh += z * bBStr; Bl += z * bBStr;
    if (oGh) { oGh += z * oBStr; oGl += z * oBStr; }
    if (oF)  { oF  += z * oBStr; }

    int ti, tj;
    if (sym) {
        int rem = blockIdx.x;
        ti = 0;
        while (rem >= 6 - ti) { rem -= (6 - ti); ti++; }
        tj = ti + rem;
    } else {
        ti = blockIdx.x / 6;
        tj = blockIdx.x % 6;
    }
    const int ci0 = ti * 128, cj0 = tj * 128;
    const int Kb16 = K >> 4;
    const int NS = K >> 5;              // k32 slabs

    // copy roles: warp q in {Ah, Al, Bh, Bl}; per slab each warp moves 8KB
    // (8 rowblocks x 2 kblocks x 512B), 16 cp.async of 16B per thread.
    const int q = wid, t5 = lane;
    const uint32_t* gq = (q == 0) ? Ah : (q == 1) ? Al : (q == 2) ? Bh : Bl;
    const int rowblk0 = ((q < 2) ? ci0 : cj0) >> 4;
    const uint32_t* gsrc = gq + (long long)rowblk0 * Kb16 * 128 + t5 * 4;
    const uint32_t sdst0 = smem_base + q * 8192 + t5 * 16;

    float acc[4][8][4];
#pragma unroll
    for (int a = 0; a < 4; a++)
#pragma unroll
        for (int b = 0; b < 8; b++)
#pragma unroll
            for (int c = 0; c < 4; c++) acc[a][b][c] = 0.f;

    // prologue: stages 0,1 (slabs 0,1)
#pragma unroll
    for (int s = 0; s < STAGES - 1; s++) {
        const uint32_t d = sdst0 + s * STAGE_BYTES;
#pragma unroll
        for (int mb = 0; mb < 8; mb++)
#pragma unroll
            for (int kb = 0; kb < 2; kb++)
                cp16(d + mb * 1024 + kb * 512,
                     gsrc + (long long)mb * Kb16 * 128 + (2 * s + kb) * 128);
        CP_COMMIT();
    }

    int sidx = 0, pidx = STAGES - 1;
    for (int s = 0; s < NS; s++) {
        if (s + STAGES - 1 < NS) {
            const int sp = s + STAGES - 1;
            const uint32_t d = sdst0 + pidx * STAGE_BYTES;
#pragma unroll
            for (int mb = 0; mb < 8; mb++)
#pragma unroll
                for (int kb = 0; kb < 2; kb++)
                    cp16(d + mb * 1024 + kb * 512,
                         gsrc + (long long)mb * Kb16 * 128 + (2 * sp + kb) * 128);
        }
        CP_COMMIT();
        CP_WAIT(STAGES - 1);
        __syncthreads();

        const uint32_t st = smem_base + sidx * STAGE_BYTES;
#pragma unroll
        for (int kb = 0; kb < 2; kb++) {
            uint4 bhv[4], blv[4];
#pragma unroll
            for (int nb = 0; nb < 4; nb++) {
                const uint32_t ba = st + (wnn * 4 + nb) * 1024 + kb * 512 + lane * 16;
                bhv[nb] = lds128(ba + 16384);
                blv[nb] = lds128(ba + 24576);
            }
#pragma unroll
            for (int mi = 0; mi < 4; mi++) {
                const uint32_t aa = st + (wm * 4 + mi) * 1024 + kb * 512 + lane * 16;
                uint4 ah = lds128(aa);
                uint4 al = lds128(aa + 8192);
#pragma unroll
                for (int nb = 0; nb < 4; nb++) {
                    uint32_t bh0[2] = {bhv[nb].x, bhv[nb].z};
                    uint32_t bl0[2] = {blv[nb].x, blv[nb].z};
                    uint32_t bh1[2] = {bhv[nb].y, bhv[nb].w};
                    uint32_t bl1[2] = {blv[nb].y, blv[nb].w};
                    float* a0 = acc[mi][nb * 2];
                    float* a1 = acc[mi][nb * 2 + 1];
                    mma_bf16(a0, (const uint32_t*)&ah, bh0);
                    mma_bf16(a0, (const uint32_t*)&al, bh0);
                    mma_bf16(a0, (const uint32_t*)&ah, bl0);
                    mma_bf16(a1, (const uint32_t*)&ah, bh1);
                    mma_bf16(a1, (const uint32_t*)&al, bh1);
                    mma_bf16(a1, (const uint32_t*)&ah, bl1);
                }
            }
        }
        __syncthreads();
        if (++sidx == STAGES) sidx = 0;
        if (++pidx == STAGES) pidx = 0;
    }

    if (!sym) {
        // row-major f32 epilogue (U)
#pragma unroll
        for (int mi = 0; mi < 4; mi++) {
            const int r = ci0 + wm * 64 + mi * 16 + grp;
#pragma unroll
            for (int nj = 0; nj < 8; nj++) {
                const int c = cj0 + wnn * 64 + (nj >> 1) * 16 + (nj & 1) * 8 + 2 * qid;
                *(float2*)&oF[(long long)r * DIMC + c] =
                    make_float2(acc[mi][nj][0], acc[mi][nj][1]);
                *(float2*)&oF[(long long)(r + 8) * DIMC + c] =
                    make_float2(acc[mi][nj][2], acc[mi][nj][3]);
            }
        }
        return;
    }

    // sym epilogue: stage via smem in two 64-row halves, write bf16-packed G
    CP_WAIT(0);
    __syncthreads();
    float* Cst = (float*)smem;   // [64][133]

    for (int h = 0; h < 2; h++) {
        if (wm == h) {
#pragma unroll
            for (int mi = 0; mi < 4; mi++) {
                const int lr = mi * 16 + grp;
#pragma unroll
                for (int nj = 0; nj < 8; nj++) {
                    const int c = wnn * 64 + (nj >> 1) * 16 + (nj & 1) * 8 + 2 * qid;
                    Cst[lr * 133 + c]           = acc[mi][nj][0];
                    Cst[lr * 133 + c + 1]       = acc[mi][nj][1];
                    Cst[(lr + 8) * 133 + c]     = acc[mi][nj][2];
                    Cst[(lr + 8) * 133 + c + 1] = acc[mi][nj][3];
                }
            }
        }
        __syncthreads();

        // direct: rows [ci0+h*64, +64) x cols [cj0, +128) -> 1024 uint4
#pragma unroll
        for (int it = 0; it < 8; it++) {
            const int u = it * 128 + tid;
            const int blk = u >> 5, l4 = u & 31;
            const int mbq = blk >> 3, kbq = blk & 7;
            const int rl = mbq * 16 + (l4 >> 2);
            const int kl = kbq * 16 + (l4 & 3) * 2;
            uint4 H, L;
            split2_bf16(Cst[rl * 133 + kl],           Cst[rl * 133 + kl + 1],       H.x, L.x);
            split2_bf16(Cst[(rl + 8) * 133 + kl],     Cst[(rl + 8) * 133 + kl + 1], H.y, L.y);
            split2_bf16(Cst[rl * 133 + kl + 8],       Cst[rl * 133 + kl + 9],       H.z, L.z);
            split2_bf16(Cst[(rl + 8) * 133 + kl + 8], Cst[(rl + 8) * 133 + kl + 9], H.w, L.w);
            const long long gi =
                ((long long)(((ci0 + h * 64) >> 4) + mbq) * 48 + (cj0 >> 4) + kbq) * 32 + l4;
            ((uint4*)oGh)[gi] = H;
            ((uint4*)oGl)[gi] = L;
        }

        if (ti != tj) {
            // mirror: rows [cj0, +128) x k [ci0+h*64, +64) -> 1024 uint4
#pragma unroll
            for (int it = 0; it < 8; it++) {
                const int u = it * 128 + tid;
                const int blk = u >> 5, l4 = u & 31;
                const int mbq = blk >> 2, kbq = blk & 3;
                const int cl = mbq * 16 + (l4 >> 2);       // local col (pack row)
                const int kl = kbq * 16 + (l4 & 3) * 2;    // local row (pack k)
                uint4 H, L;
                split2_bf16(Cst[kl * 133 + cl],           Cst[(kl + 1) * 133 + cl],     H.x, L.x);
                split2_bf16(Cst[kl * 133 + cl + 8],       Cst[(kl + 1) * 133 + cl + 8], H.y, L.y);
                split2_bf16(Cst[(kl + 8) * 133 + cl],     Cst[(kl + 9) * 133 + cl],     H.z, L.z);
                split2_bf16(Cst[(kl + 8) * 133 + cl + 8], Cst[(kl + 9) * 133 + cl + 8], H.w, L.w);
                const long long gi =
                    ((long long)((cj0 >> 4) + mbq) * 48 + (((ci0 + h * 64) >> 4) + kbq)) * 32 + l4;
                ((uint4*)oGh)[gi] = H;
                ((uint4*)oGl)[gi] = L;
            }
        }
        __syncthreads();
    }
}

// ---------------------------------------------------------------------------
// Per (m,b,h): L[d][e] = SCALE * sum_c U[h*64+d][c] * W[c][768+h*64+e]
// then column-wise (over d) softmax -> g_ctx[m][b][h]
// ---------------------------------------------------------------------------
__global__ __launch_bounds__(256) void ctx_kernel(
    const float* __restrict__ Wrgb, const float* __restrict__ Wdepth)
{
    __shared__ float Us[64][68];
    __shared__ float Ws[64][68];

    const int z = blockIdx.y;
    const int m = z >> 4, b = z & 15;
    const int h = blockIdx.x;
    const float* U = &g_U[m][b][0] + (long long)(h * 64) * DIMC;
    const float* W = (m == 0 ? Wrgb : Wdepth) + DIMC + h * 64;

    const int tid = threadIdx.x;
    const int ty = tid >> 4, tx = tid & 15;

    float acc[4][4];
#pragma unroll
    for (int i = 0; i < 4; i++)
#pragma unroll
        for (int j = 0; j < 4; j++) acc[i][j] = 0.f;

    for (int c0 = 0; c0 < DIMC; c0 += 64) {
#pragma unroll
        for (int t = 0; t < 4; t++) {
            const int f4 = tid + t * 256;
            const int r = f4 >> 4;
            const int cg = (f4 & 15) << 2;
            float4 u = *(const float4*)(U + (long long)r * DIMC + c0 + cg);
            Us[r][cg + 0] = u.x; Us[r][cg + 1] = u.y; Us[r][cg + 2] = u.z; Us[r][cg + 3] = u.w;
            float4 w = *(const float4*)(W + (long long)(c0 + r) * (2 * DIMC) + cg);
            Ws[r][cg + 0] = w.x; Ws[r][cg + 1] = w.y; Ws[r][cg + 2] = w.z; Ws[r][cg + 3] = w.w;
        }
        __syncthreads();
#pragma unroll 8
        for (int c = 0; c < 64; c++) {
            float u0 = Us[ty * 4 + 0][c], u1 = Us[ty * 4 + 1][c];
            float u2 = Us[ty * 4 + 2][c], u3 = Us[ty * 4 + 3][c];
            float w0 = Ws[c][tx * 4 + 0], w1 = Ws[c][tx * 4 + 1];
            float w2 = Ws[c][tx * 4 + 2], w3 = Ws[c][tx * 4 + 3];
            acc[0][0] += u0 * w0; acc[0][1] += u0 * w1; acc[0][2] += u0 * w2; acc[0][3] += u0 * w3;
            acc[1][0] += u1 * w0; acc[1][1] += u1 * w1; acc[1][2] += u1 * w2; acc[1][3] += u1 * w3;
            acc[2][0] += u2 * w0; acc[2][1] += u2 * w1; acc[2][2] += u2 * w2; acc[2][3] += u2 * w3;
            acc[3][0] += u3 * w0; acc[3][1] += u3 * w1; acc[3][2] += u3 * w2; acc[3][3] += u3 * w3;
        }
        __syncthreads();
    }

    const float SCALE = 0.125f;
#pragma unroll
    for (int i = 0; i < 4; i++)
#pragma unroll
        for (int j = 0; j < 4; j++)
            Us[ty * 4 + i][tx * 4 + j] = acc[i][j] * SCALE;
    __syncthreads();

    if (tid < 64) {
        const int e = tid;
        float mx = -1e30f;
#pragma unroll 8
        for (int d = 0; d < 64; d++) mx = fmaxf(mx, Us[d][e]);
        float s = 0.f;
#pragma unroll 8
        for (int d = 0; d < 64; d++) {
            float v = expf(Us[d][e] - mx);
            Us[d][e] = v;
            s += v;
        }
        const float inv = 1.f / s;
        float* cx = &g_ctx[m][b][h][0];
#pragma unroll 8
        for (int d = 0; d < 64; d++) cx[d * 64 + e] = Us[d][e] * inv;
    }
}

// ---------------------------------------------------------------------------
// out_m[b, n, h*64+e] = sum_d X_m[b, n, h*64+d] * ctx_{1-m}[b][h][d][e]
// 128-row tiles, tf32 mma, K=64. Dynamic smem: As[128][68] u32, Bs[64][68].
// ---------------------------------------------------------------------------
__global__ __launch_bounds__(256) void out_kernel(
    const float* __restrict__ rgb, const float* __restrict__ depth,
    float* __restrict__ out)
{
    extern __shared__ char smem[];
    uint32_t* As = (uint32_t*)smem;                 // [128][68]
    uint32_t* Bs = (uint32_t*)smem + 128 * 68;      // [64][68]

    const int z = blockIdx.z;
    const int m = z >> 4, b = z & 15;
    const int h = blockIdx.y;
    const int n0 = blockIdx.x * 128;

    const float* X = (m == 0 ? rgb : depth) + ((long long)b * NTOK + n0) * DIMC + h * HD;
    const float* cx = &g_ctx[1 - m][b][h][0];
    float* O = out + (long long)m * BATCH * NTOK * DIMC + ((long long)b * NTOK + n0) * DIMC + h * HD;

    const int tid = threadIdx.x;
    const int wid = tid >> 5, lane = tid & 31;
    const int wm = wid >> 2, wn = wid & 3;
    const int grp = lane >> 2, qid = lane & 3;

#pragma unroll
    for (int t = 0; t < 8; t++) {
        const int f4 = tid + t * 256;
        const int r = f4 >> 4;
        const int cg = (f4 & 15) << 2;
        float4 v = *(const float4*)(X + (long long)r * DIMC + cg);
        As[r * 68 + cg + 0] = to_tf32(v.x); As[r * 68 + cg + 1] = to_tf32(v.y);
        As[r * 68 + cg + 2] = to_tf32(v.z); As[r * 68 + cg + 3] = to_tf32(v.w);
    }
#pragma unroll
    for (int t = 0; t < 4; t++) {
        const int f4 = tid + t * 256;
        const int d = f4 >> 4;
        const int eg = (f4 & 15) << 2;
        float4 v = *(const float4*)(cx + d * 64 + eg);
        Bs[(eg + 0) * 68 + d] = to_tf32(v.x); Bs[(eg + 1) * 68 + d] = to_tf32(v.y);
        Bs[(eg + 2) * 68 + d] = to_tf32(v.z); Bs[(eg + 3) * 68 + d] = to_tf32(v.w);
    }
    __syncthreads();

    float acc[4][2][4];
#pragma unroll
    for (int a = 0; a < 4; a++)
#pragma unroll
        for (int c = 0; c < 2; c++)
#pragma unroll
            for (int r = 0; r < 4; r++) acc[a][c][r] = 0.f;

#pragma unroll
    for (int ks = 0; ks < 8; ks++) {
        const int kq = (ks << 3) + qid;
        uint32_t ah[4][4], bh[2][2];
#pragma unroll
        for (int mi = 0; mi < 4; mi++) {
            const int i = wm * 64 + mi * 16 + grp;
            ah[mi][0] = As[i * 68 + kq];           ah[mi][1] = As[(i + 8) * 68 + kq];
            ah[mi][2] = As[i * 68 + kq + 4];       ah[mi][3] = As[(i + 8) * 68 + kq + 4];
        }
#pragma unroll
        for (int nj = 0; nj < 2; nj++) {
            const int n = wn * 16 + nj * 8 + grp;
            bh[nj][0] = Bs[n * 68 + kq]; bh[nj][1] = Bs[n * 68 + kq + 4];
        }
#pragma unroll
        for (int mi = 0; mi < 4; mi++)
#pragma unroll
            for (int nj = 0; nj < 2; nj++)
                mma_tf32(acc[mi][nj], ah[mi], bh[nj]);
    }

#pragma unroll
    for (int mi = 0; mi < 4; mi++) {
        const int r0 = wm * 64 + mi * 16 + grp;
#pragma unroll
        for (int nj = 0; nj < 2; nj++) {
            const int c0c = wn * 16 + nj * 8 + 2 * qid;
            *(float2*)(O + (long long)r0 * DIMC + c0c) =
                make_float2(acc[mi][nj][0], acc[mi][nj][1]);
            *(float2*)(O + (long long)(r0 + 8) * DIMC + c0c) =
                make_float2(acc[mi][nj][2], acc[mi][nj][3]);
        }
    }
}

// ---------------------------------------------------------------------------
extern "C" void kernel_launch(void* const* d_in, const int* in_sizes, int n_in,
                              void* d_out, int out_size)
{
    const float* rgb = (const float*)d_in[0];
    const float* dep = (const float*)d_in[1];
    const float* Wr  = (const float*)d_in[2];
    const float* Wd  = (const float*)d_in[3];
    float* out = (float*)d_out;

    uint32_t *pXh, *pXl, *pWh, *pWl, *pGh, *pGl;
    float *pU;
    cudaGetSymbolAddress((void**)&pXh, g_Xh);
    cudaGetSymbolAddress((void**)&pXl, g_Xl);
    cudaGetSymbolAddress((void**)&pWh, g_Wh);
    cudaGetSymbolAddress((void**)&pWl, g_Wl);
    cudaGetSymbolAddress((void**)&pGh, g_Gh);
    cudaGetSymbolAddress((void**)&pGl, g_Gl);
    cudaGetSymbolAddress((void**)&pU, g_U);

    cudaFuncSetAttribute(gemm_bf16_kernel,
                         cudaFuncAttributeMaxDynamicSharedMemorySize, GEMM_SMEM);
    cudaFuncSetAttribute(out_kernel,
                         cudaFuncAttributeMaxDynamicSharedMemorySize, OUT_SMEM);

    const long long XS  = (long long)NTOK * DIMC;          // per-batch X floats
    const long long XPB = (long long)DIMC * (NTOK / 2);    // per-batch packed u32
    const long long GPB = (long long)DIMC * (DIMC / 2);    // per-batch packed G u32
    const long long WPB = (long long)DIMC * (DIMC / 2);
    const long long UB  = (long long)DIMC * DIMC;

    // pre-pass: bf16 split + fragment pack (merged: z covers both modalities)
    pack_bf16_kernel<<<dim3(12, 64, 32), 256>>>(rgb, dep, XS, DIMC, NTOK, 16,
                                                pXh, pXl, XPB);
    pack_bf16_kernel<<<dim3(12, 12, 2), 256>>>(Wr, Wd, 0, 2 * DIMC, DIMC, 1,
                                               pWh, pWl, WPB);

    // G = XᵀX (symmetric, 21 tiles x 32 batch-modality), packed bf16 G out
    gemm_bf16_kernel<<<dim3(21, 32), 128, GEMM_SMEM>>>(
        pXh, pXl, XPB, 1, pXh, pXl, XPB, NTOK, 1, pGh, pGl, nullptr, GPB);

    // U = Wkᵀ G (36 tiles x 32), f32 U out
    gemm_bf16_kernel<<<dim3(36, 32), 128, GEMM_SMEM>>>(
        pWh, pWl, WPB, 16, pGh, pGl, GPB, DIMC, 0, nullptr, nullptr, pU, UB);

    // per-head logits + softmax -> ctx
    ctx_kernel<<<dim3(NHEADS, 32), 256>>>(Wr, Wd);

    // out = X @ blockdiag(ctx_other), 128-row tiles
    out_kernel<<<dim3(NTOK / 128, NHEADS, 32), 256, OUT_SMEM>>>(rgb, dep, out);
}